// round 1
// baseline (speedup 1.0000x reference)
#include <cuda_runtime.h>

#define B_  2
#define S_  2048
#define E_  1024
#define H_  16
#define D_  64
#define M_  (B_*S_)   /* 4096 */
#define K_  E_        /* 1024 */
#define N_  E_        /* 1024 */

// Scratch (device globals: no allocation allowed)
__device__ float g_q[B_*H_*S_*D_];
__device__ float g_k[B_*H_*S_*D_];
__device__ float g_v[B_*H_*S_*D_];
__device__ float g_a[B_*S_*E_];

// ---------------------------------------------------------------------------
// GEMM: C[M,N] = A[M,K] @ W[N,K]^T + bias[N]
// PERM=0: C row-major [M,N]. PERM=1: scatter to [B,H,S,D] (QKV layout).
// Tiles 128x128x16, 256 threads, 8x8 per thread.
// ---------------------------------------------------------------------------
template<int PERM>
__global__ __launch_bounds__(256)
void gemm_nt(const float* __restrict__ A, const float* __restrict__ W,
             const float* __restrict__ bias, float* __restrict__ C)
{
    __shared__ float As[16][132];
    __shared__ float Bs[16][132];

    const int tid = threadIdx.x;
    const int tx  = tid & 15;
    const int ty  = tid >> 4;
    const int m0  = blockIdx.y * 128;
    const int n0  = blockIdx.x * 128;

    const int lr = tid >> 2;         // 0..63
    const int lc = (tid & 3) * 4;    // 0,4,8,12

    float acc[8][8];
    #pragma unroll
    for (int i = 0; i < 8; i++)
        #pragma unroll
        for (int j = 0; j < 8; j++) acc[i][j] = 0.f;

    for (int k0 = 0; k0 < K_; k0 += 16) {
        float4 a0 = *(const float4*)(A + (size_t)(m0 + lr     ) * K_ + k0 + lc);
        float4 a1 = *(const float4*)(A + (size_t)(m0 + lr + 64) * K_ + k0 + lc);
        float4 b0 = *(const float4*)(W + (size_t)(n0 + lr     ) * K_ + k0 + lc);
        float4 b1 = *(const float4*)(W + (size_t)(n0 + lr + 64) * K_ + k0 + lc);

        __syncthreads();
        As[lc+0][lr]    = a0.x; As[lc+1][lr]    = a0.y; As[lc+2][lr]    = a0.z; As[lc+3][lr]    = a0.w;
        As[lc+0][lr+64] = a1.x; As[lc+1][lr+64] = a1.y; As[lc+2][lr+64] = a1.z; As[lc+3][lr+64] = a1.w;
        Bs[lc+0][lr]    = b0.x; Bs[lc+1][lr]    = b0.y; Bs[lc+2][lr]    = b0.z; Bs[lc+3][lr]    = b0.w;
        Bs[lc+0][lr+64] = b1.x; Bs[lc+1][lr+64] = b1.y; Bs[lc+2][lr+64] = b1.z; Bs[lc+3][lr+64] = b1.w;
        __syncthreads();

        #pragma unroll
        for (int k = 0; k < 16; k++) {
            float ar[8], br[8];
            *(float4*)&ar[0] = *(const float4*)&As[k][ty*4];
            *(float4*)&ar[4] = *(const float4*)&As[k][64 + ty*4];
            *(float4*)&br[0] = *(const float4*)&Bs[k][tx*4];
            *(float4*)&br[4] = *(const float4*)&Bs[k][64 + tx*4];
            #pragma unroll
            for (int i = 0; i < 8; i++)
                #pragma unroll
                for (int j = 0; j < 8; j++)
                    acc[i][j] += ar[i] * br[j];
        }
    }

    // epilogue
    float bs[8];
    #pragma unroll
    for (int j = 0; j < 4; j++) {
        bs[j]     = bias[n0 + tx*4 + j];
        bs[4 + j] = bias[n0 + 64 + tx*4 + j];
    }

    #pragma unroll
    for (int i = 0; i < 8; i++) {
        const int m = m0 + ((i < 4) ? (ty*4 + i) : (64 + ty*4 + i - 4));
        #pragma unroll
        for (int j = 0; j < 8; j++) {
            const int n = n0 + ((j < 4) ? (tx*4 + j) : (64 + tx*4 + j - 4));
            const float v = acc[i][j] + bs[j];
            if (PERM) {
                const int b = m >> 11;         // /S_
                const int s = m & (S_ - 1);
                const int h = n >> 6;          // /64
                const int d = n & 63;
                C[(((size_t)((b << 4) + h)) * S_ + s) * 64 + d] = v;
            } else {
                C[(size_t)m * N_ + n] = v;
            }
        }
    }
}

// ---------------------------------------------------------------------------
// RoPE applied in-place to g_q and g_k. One thread per (bh, s, d<32) pair.
// ---------------------------------------------------------------------------
__global__ __launch_bounds__(256)
void rope_kernel(const float* __restrict__ cosT, const float* __restrict__ sinT)
{
    const int idx = blockIdx.x * blockDim.x + threadIdx.x;   // 2^21 threads
    const int d  = idx & 31;
    const int s  = (idx >> 5) & (S_ - 1);
    const int bh = idx >> 16;                                 // 0..31

    const float c1 = cosT[s*64 + d];
    const float s1 = sinT[s*64 + d];
    const float c2 = cosT[s*64 + d + 32];
    const float s2 = sinT[s*64 + d + 32];

    const size_t base = ((size_t)bh * S_ + s) * 64 + d;

    float q1 = g_q[base], q2 = g_q[base + 32];
    g_q[base]      = q1 * c1 - q2 * s1;
    g_q[base + 32] = q2 * c2 + q1 * s2;

    float k1 = g_k[base], k2 = g_k[base + 32];
    g_k[base]      = k1 * c1 - k2 * s1;
    g_k[base + 32] = k2 * c2 + k1 * s2;
}

// ---------------------------------------------------------------------------
// Causal flash attention. Block = 128 threads (4 warps), 8 query rows/block
// (2 per warp). Key tiles of 64 in smem (stride 65 -> conflict-free).
// Lanes are key-parallel (2 keys each), per-lane online softmax,
// cross-lane merge at the end. Output to g_a in [B,S,H*D] layout.
// ---------------------------------------------------------------------------
__global__ __launch_bounds__(128)
void attn_kernel()
{
    __shared__ float sK[64][65];
    __shared__ float sV[64][65];
    __shared__ float sQ[8][64];

    const int tid  = threadIdx.x;
    const int w    = tid >> 5;
    const int lane = tid & 31;
    const int bh   = blockIdx.y;            // b*16 + h
    const int q0   = blockIdx.x * 8;

    const float* Qb = g_q + (size_t)bh * S_ * 64;
    const float* Kb = g_k + (size_t)bh * S_ * 64;
    const float* Vb = g_v + (size_t)bh * S_ * 64;

    // load + pre-scale Q rows
    for (int i = tid; i < 8 * 64; i += 128) {
        const int r = i >> 6, d = i & 63;
        sQ[r][d] = Qb[(size_t)(q0 + r) * 64 + d] * 0.125f;
    }

    const int r0 = 2*w, r1 = 2*w + 1;
    const int qrow0 = q0 + r0, qrow1 = q0 + r1;

    float m0 = -1e30f, m1 = -1e30f;
    float l0 = 0.f,    l1 = 0.f;
    float acc0[64], acc1[64];
    #pragma unroll
    for (int d = 0; d < 64; d++) { acc0[d] = 0.f; acc1[d] = 0.f; }

    const int ntiles = (q0 + 7) / 64 + 1;
    for (int t = 0; t < ntiles; t++) {
        const int kb = t * 64;
        __syncthreads();
        // cooperative K/V tile load (float4 from gmem, scalar scatter to padded smem)
        #pragma unroll
        for (int i = 0; i < 8; i++) {
            const int idx = tid + i * 128;          // float4 id 0..1023
            const int j  = idx >> 4;
            const int dq = (idx & 15) << 2;
            float4 kv = *(const float4*)(Kb + (size_t)(kb + j) * 64 + dq);
            sK[j][dq] = kv.x; sK[j][dq+1] = kv.y; sK[j][dq+2] = kv.z; sK[j][dq+3] = kv.w;
            float4 vv = *(const float4*)(Vb + (size_t)(kb + j) * 64 + dq);
            sV[j][dq] = vv.x; sV[j][dq+1] = vv.y; sV[j][dq+2] = vv.z; sV[j][dq+3] = vv.w;
        }
        __syncthreads();

        if (kb > qrow1) continue;   // warp-uniform: whole tile masked for both rows

        const int j0 = lane, j1 = lane + 32;
        const int jg0 = kb + j0, jg1 = kb + j1;

        float s00 = 0.f, s01 = 0.f, s10 = 0.f, s11 = 0.f;   // s[key][row]
        #pragma unroll
        for (int d = 0; d < 64; d++) {
            const float qa = sQ[r0][d];
            const float qb = sQ[r1][d];
            const float k0v = sK[j0][d];
            const float k1v = sK[j1][d];
            s00 += qa * k0v;  s01 += qb * k0v;
            s10 += qa * k1v;  s11 += qb * k1v;
        }

        const bool v00 = (jg0 <= qrow0), v01 = (jg0 <= qrow1);
        const bool v10 = (jg1 <= qrow0), v11 = (jg1 <= qrow1);
        if (!v00) s00 = -1e30f;
        if (!v01) s01 = -1e30f;
        if (!v10) s10 = -1e30f;
        if (!v11) s11 = -1e30f;

        // row 0 online update
        const float nm0 = fmaxf(m0, fmaxf(s00, s10));
        const float c0  = __expf(m0 - nm0);
        const float p00 = v00 ? __expf(s00 - nm0) : 0.f;
        const float p10 = v10 ? __expf(s10 - nm0) : 0.f;
        l0 = l0 * c0 + p00 + p10;
        m0 = nm0;
        // row 1 online update
        const float nm1 = fmaxf(m1, fmaxf(s01, s11));
        const float c1  = __expf(m1 - nm1);
        const float p01 = v01 ? __expf(s01 - nm1) : 0.f;
        const float p11 = v11 ? __expf(s11 - nm1) : 0.f;
        l1 = l1 * c1 + p01 + p11;
        m1 = nm1;

        #pragma unroll
        for (int d = 0; d < 64; d++) {
            const float v0 = sV[j0][d];
            const float v1 = sV[j1][d];
            acc0[d] = acc0[d] * c0 + p00 * v0 + p10 * v1;
            acc1[d] = acc1[d] * c1 + p01 * v0 + p11 * v1;
        }
    }

    // cross-lane merge + output
    const int b = bh >> 4;
    const int h = bh & 15;
    float* Ob0 = g_a + ((size_t)b * S_ + qrow0) * E_ + h * 64;
    float* Ob1 = g_a + ((size_t)b * S_ + qrow1) * E_ + h * 64;

    // row 0
    {
        float M = m0;
        #pragma unroll
        for (int o = 16; o; o >>= 1) M = fmaxf(M, __shfl_xor_sync(0xFFFFFFFFu, M, o));
        const float f = __expf(m0 - M);
        float L = l0 * f;
        #pragma unroll
        for (int o = 16; o; o >>= 1) L += __shfl_xor_sync(0xFFFFFFFFu, L, o);
        const float invL = 1.f / L;
        #pragma unroll
        for (int d = 0; d < 64; d++) {
            float v = acc0[d] * f;
            #pragma unroll
            for (int o = 16; o; o >>= 1) v += __shfl_xor_sync(0xFFFFFFFFu, v, o);
            if (lane == (d & 31)) Ob0[d] = v * invL;
        }
    }
    // row 1
    {
        float M = m1;
        #pragma unroll
        for (int o = 16; o; o >>= 1) M = fmaxf(M, __shfl_xor_sync(0xFFFFFFFFu, M, o));
        const float f = __expf(m1 - M);
        float L = l1 * f;
        #pragma unroll
        for (int o = 16; o; o >>= 1) L += __shfl_xor_sync(0xFFFFFFFFu, L, o);
        const float invL = 1.f / L;
        #pragma unroll
        for (int d = 0; d < 64; d++) {
            float v = acc1[d] * f;
            #pragma unroll
            for (int o = 16; o; o >>= 1) v += __shfl_xor_sync(0xFFFFFFFFu, v, o);
            if (lane == (d & 31)) Ob1[d] = v * invL;
        }
    }
}

// ---------------------------------------------------------------------------
// Inputs (metadata order): 0=x 1=mask 2=cos 3=sin 4=Wq 5=bq 6=Wk 7=bk
//                          8=Wv 9=bv 10=Wo 11=bo
// ---------------------------------------------------------------------------
extern "C" void kernel_launch(void* const* d_in, const int* in_sizes, int n_in,
                              void* d_out, int out_size)
{
    const float* x    = (const float*)d_in[0];
    const float* cosT = (const float*)d_in[2];
    const float* sinT = (const float*)d_in[3];
    const float* Wq   = (const float*)d_in[4];
    const float* bq   = (const float*)d_in[5];
    const float* Wk   = (const float*)d_in[6];
    const float* bk   = (const float*)d_in[7];
    const float* Wv   = (const float*)d_in[8];
    const float* bv   = (const float*)d_in[9];
    const float* Wo   = (const float*)d_in[10];
    const float* bo   = (const float*)d_in[11];
    float* out = (float*)d_out;

    float *qp, *kp, *vp, *ap;
    cudaGetSymbolAddress((void**)&qp, g_q);
    cudaGetSymbolAddress((void**)&kp, g_k);
    cudaGetSymbolAddress((void**)&vp, g_v);
    cudaGetSymbolAddress((void**)&ap, g_a);

    const dim3 gg(N_ / 128, M_ / 128);   // (8, 32)
    gemm_nt<1><<<gg, 256>>>(x, Wq, bq, qp);
    gemm_nt<1><<<gg, 256>>>(x, Wk, bk, kp);
    gemm_nt<1><<<gg, 256>>>(x, Wv, bv, vp);

    rope_kernel<<<(B_*H_*S_*32) / 256, 256>>>(cosT, sinT);

    attn_kernel<<<dim3(S_ / 8, B_ * H_), 128>>>();

    gemm_nt<0><<<gg, 256>>>(ap, Wo, bo, out);
}

// round 2
// speedup vs baseline: 1.0309x; 1.0309x over previous
#include <cuda_runtime.h>
#include <mma.h>

using namespace nvcuda;

#define B_  2
#define S_  2048
#define E_  1024
#define H_  16
#define D_  64
#define M_  (B_*S_)   /* 4096 */
#define K_  E_        /* 1024 */
#define N_  E_        /* 1024 */

// Scratch (device globals: no allocation allowed)
__device__ float g_q[B_*H_*S_*D_];
__device__ float g_k[B_*H_*S_*D_];
__device__ float g_v[B_*H_*S_*D_];
__device__ float g_a[B_*S_*E_];

// ---------------------------------------------------------------------------
// tf32 tensor-core GEMM: C[M,N] = A[M,K] @ W[N,K]^T + bias[N]
// PERM=0: row-major [M,N].  PERM=1: scatter to [B,H,S,D] (per-fragment stores
// are still dense row-major with ld=64 because 16x16 tiles never cross a
// head (64-col) or batch (2048-row) boundary).
// Block tile 128x128, K-chunk 32, 8 warps (2x4), warp tile 64x32.
// ---------------------------------------------------------------------------
template<int PERM>
__global__ __launch_bounds__(256)
void gemm_tf32(const float* __restrict__ A, const float* __restrict__ W,
               const float* __restrict__ bias, float* __restrict__ C)
{
    __shared__ float As[128][36];      // [m][k] row-major, lda=36
    __shared__ float Bs[128][36];      // [n][k] -> col-major view of B[k][n], ldb=36
    __shared__ float biasS[16][128];   // bias replicated over 16 rows

    const int tid = threadIdx.x;
    const int wid = tid >> 5;
    const int wm  = wid >> 2;          // 0..1  (M dir, 64 rows each)
    const int wn  = wid & 3;           // 0..3  (N dir, 32 cols each)
    const int m0  = blockIdx.y * 128;
    const int n0  = blockIdx.x * 128;

    // stage replicated bias
    for (int i = tid; i < 16 * 128; i += 256) {
        biasS[i >> 7][i & 127] = bias[n0 + (i & 127)];
    }
    __syncthreads();

    wmma::fragment<wmma::accumulator, 16, 16, 8, float> c_frag[4][2];
    #pragma unroll
    for (int i = 0; i < 4; i++)
        #pragma unroll
        for (int j = 0; j < 2; j++)
            wmma::load_matrix_sync(c_frag[i][j], &biasS[0][wn*32 + j*16], 128,
                                   wmma::mem_row_major);

    wmma::fragment<wmma::matrix_a, 16, 16, 8, wmma::precision::tf32, wmma::row_major> a_frag[4];
    wmma::fragment<wmma::matrix_b, 16, 16, 8, wmma::precision::tf32, wmma::col_major> b_frag[2];

    for (int k0 = 0; k0 < K_; k0 += 32) {
        __syncthreads();
        // stage A and B chunks, pre-rounded to tf32 (idempotent under HW truncation)
        #pragma unroll
        for (int it = 0; it < 4; it++) {
            const int f   = tid + it * 256;     // float4 index 0..1023
            const int row = f >> 3;
            const int c4  = (f & 7) << 2;
            float4 av = *(const float4*)(A + (size_t)(m0 + row) * K_ + k0 + c4);
            av.x = wmma::__float_to_tf32(av.x); av.y = wmma::__float_to_tf32(av.y);
            av.z = wmma::__float_to_tf32(av.z); av.w = wmma::__float_to_tf32(av.w);
            *(float4*)&As[row][c4] = av;
            float4 bv = *(const float4*)(W + (size_t)(n0 + row) * K_ + k0 + c4);
            bv.x = wmma::__float_to_tf32(bv.x); bv.y = wmma::__float_to_tf32(bv.y);
            bv.z = wmma::__float_to_tf32(bv.z); bv.w = wmma::__float_to_tf32(bv.w);
            *(float4*)&Bs[row][c4] = bv;
        }
        __syncthreads();

        #pragma unroll
        for (int kk = 0; kk < 32; kk += 8) {
            #pragma unroll
            for (int i = 0; i < 4; i++)
                wmma::load_matrix_sync(a_frag[i], &As[wm*64 + i*16][kk], 36);
            #pragma unroll
            for (int j = 0; j < 2; j++)
                wmma::load_matrix_sync(b_frag[j], &Bs[wn*32 + j*16][kk], 36);
            #pragma unroll
            for (int i = 0; i < 4; i++)
                #pragma unroll
                for (int j = 0; j < 2; j++)
                    wmma::mma_sync(c_frag[i][j], a_frag[i], b_frag[j], c_frag[i][j]);
        }
    }

    #pragma unroll
    for (int i = 0; i < 4; i++) {
        const int mt = m0 + wm*64 + i*16;
        #pragma unroll
        for (int j = 0; j < 2; j++) {
            const int nt = n0 + wn*32 + j*16;
            if (PERM) {
                const int b = mt >> 11;
                const int s = mt & (S_ - 1);
                const int h = nt >> 6;
                const int d = nt & 63;
                float* p = C + (((size_t)((b << 4) + h)) * S_ + s) * 64 + d;
                wmma::store_matrix_sync(p, c_frag[i][j], 64, wmma::mem_row_major);
            } else {
                float* p = C + (size_t)mt * N_ + nt;
                wmma::store_matrix_sync(p, c_frag[i][j], N_, wmma::mem_row_major);
            }
        }
    }
}

// ---------------------------------------------------------------------------
// RoPE applied in-place to g_q and g_k. One thread per (bh, s, d<32) pair.
// ---------------------------------------------------------------------------
__global__ __launch_bounds__(256)
void rope_kernel(const float* __restrict__ cosT, const float* __restrict__ sinT)
{
    const int idx = blockIdx.x * blockDim.x + threadIdx.x;   // 2^21 threads
    const int d  = idx & 31;
    const int s  = (idx >> 5) & (S_ - 1);
    const int bh = idx >> 16;                                 // 0..31

    const float c1 = cosT[s*64 + d];
    const float s1 = sinT[s*64 + d];
    const float c2 = cosT[s*64 + d + 32];
    const float s2 = sinT[s*64 + d + 32];

    const size_t base = ((size_t)bh * S_ + s) * 64 + d;

    float q1 = g_q[base], q2 = g_q[base + 32];
    g_q[base]      = q1 * c1 - q2 * s1;
    g_q[base + 32] = q2 * c2 + q1 * s2;

    float k1 = g_k[base], k2 = g_k[base + 32];
    g_k[base]      = k1 * c1 - k2 * s1;
    g_k[base + 32] = k2 * c2 + k1 * s2;
}

// ---------------------------------------------------------------------------
// Causal flash attention. Block = 128 threads (4 warps), 8 query rows/block
// (2 per warp). Key tiles of 64 in smem (stride 65 -> conflict-free).
// ---------------------------------------------------------------------------
__global__ __launch_bounds__(128)
void attn_kernel()
{
    __shared__ float sK[64][65];
    __shared__ float sV[64][65];
    __shared__ float sQ[8][64];

    const int tid  = threadIdx.x;
    const int w    = tid >> 5;
    const int lane = tid & 31;
    const int bh   = blockIdx.y;            // b*16 + h
    const int q0   = blockIdx.x * 8;

    const float* Qb = g_q + (size_t)bh * S_ * 64;
    const float* Kb = g_k + (size_t)bh * S_ * 64;
    const float* Vb = g_v + (size_t)bh * S_ * 64;

    for (int i = tid; i < 8 * 64; i += 128) {
        const int r = i >> 6, d = i & 63;
        sQ[r][d] = Qb[(size_t)(q0 + r) * 64 + d] * 0.125f;
    }

    const int r0 = 2*w, r1 = 2*w + 1;
    const int qrow0 = q0 + r0, qrow1 = q0 + r1;

    float m0 = -1e30f, m1 = -1e30f;
    float l0 = 0.f,    l1 = 0.f;
    float acc0[64], acc1[64];
    #pragma unroll
    for (int d = 0; d < 64; d++) { acc0[d] = 0.f; acc1[d] = 0.f; }

    const int ntiles = (q0 + 7) / 64 + 1;
    for (int t = 0; t < ntiles; t++) {
        const int kb = t * 64;
        __syncthreads();
        #pragma unroll
        for (int i = 0; i < 8; i++) {
            const int idx = tid + i * 128;
            const int j  = idx >> 4;
            const int dq = (idx & 15) << 2;
            float4 kv = *(const float4*)(Kb + (size_t)(kb + j) * 64 + dq);
            sK[j][dq] = kv.x; sK[j][dq+1] = kv.y; sK[j][dq+2] = kv.z; sK[j][dq+3] = kv.w;
            float4 vv = *(const float4*)(Vb + (size_t)(kb + j) * 64 + dq);
            sV[j][dq] = vv.x; sV[j][dq+1] = vv.y; sV[j][dq+2] = vv.z; sV[j][dq+3] = vv.w;
        }
        __syncthreads();

        if (kb > qrow1) continue;

        const int j0 = lane, j1 = lane + 32;
        const int jg0 = kb + j0, jg1 = kb + j1;

        float s00 = 0.f, s01 = 0.f, s10 = 0.f, s11 = 0.f;
        #pragma unroll
        for (int d = 0; d < 64; d++) {
            const float qa = sQ[r0][d];
            const float qb = sQ[r1][d];
            const float k0v = sK[j0][d];
            const float k1v = sK[j1][d];
            s00 += qa * k0v;  s01 += qb * k0v;
            s10 += qa * k1v;  s11 += qb * k1v;
        }

        const bool v00 = (jg0 <= qrow0), v01 = (jg0 <= qrow1);
        const bool v10 = (jg1 <= qrow0), v11 = (jg1 <= qrow1);
        if (!v00) s00 = -1e30f;
        if (!v01) s01 = -1e30f;
        if (!v10) s10 = -1e30f;
        if (!v11) s11 = -1e30f;

        const float nm0 = fmaxf(m0, fmaxf(s00, s10));
        const float c0  = __expf(m0 - nm0);
        const float p00 = v00 ? __expf(s00 - nm0) : 0.f;
        const float p10 = v10 ? __expf(s10 - nm0) : 0.f;
        l0 = l0 * c0 + p00 + p10;
        m0 = nm0;
        const float nm1 = fmaxf(m1, fmaxf(s01, s11));
        const float c1  = __expf(m1 - nm1);
        const float p01 = v01 ? __expf(s01 - nm1) : 0.f;
        const float p11 = v11 ? __expf(s11 - nm1) : 0.f;
        l1 = l1 * c1 + p01 + p11;
        m1 = nm1;

        #pragma unroll
        for (int d = 0; d < 64; d++) {
            const float v0 = sV[j0][d];
            const float v1 = sV[j1][d];
            acc0[d] = acc0[d] * c0 + p00 * v0 + p10 * v1;
            acc1[d] = acc1[d] * c1 + p01 * v0 + p11 * v1;
        }
    }

    const int b = bh >> 4;
    const int h = bh & 15;
    float* Ob0 = g_a + ((size_t)b * S_ + qrow0) * E_ + h * 64;
    float* Ob1 = g_a + ((size_t)b * S_ + qrow1) * E_ + h * 64;

    {
        float M = m0;
        #pragma unroll
        for (int o = 16; o; o >>= 1) M = fmaxf(M, __shfl_xor_sync(0xFFFFFFFFu, M, o));
        const float f = __expf(m0 - M);
        float L = l0 * f;
        #pragma unroll
        for (int o = 16; o; o >>= 1) L += __shfl_xor_sync(0xFFFFFFFFu, L, o);
        const float invL = 1.f / L;
        #pragma unroll
        for (int d = 0; d < 64; d++) {
            float v = acc0[d] * f;
            #pragma unroll
            for (int o = 16; o; o >>= 1) v += __shfl_xor_sync(0xFFFFFFFFu, v, o);
            if (lane == (d & 31)) Ob0[d] = v * invL;
        }
    }
    {
        float M = m1;
        #pragma unroll
        for (int o = 16; o; o >>= 1) M = fmaxf(M, __shfl_xor_sync(0xFFFFFFFFu, M, o));
        const float f = __expf(m1 - M);
        float L = l1 * f;
        #pragma unroll
        for (int o = 16; o; o >>= 1) L += __shfl_xor_sync(0xFFFFFFFFu, L, o);
        const float invL = 1.f / L;
        #pragma unroll
        for (int d = 0; d < 64; d++) {
            float v = acc1[d] * f;
            #pragma unroll
            for (int o = 16; o; o >>= 1) v += __shfl_xor_sync(0xFFFFFFFFu, v, o);
            if (lane == (d & 31)) Ob1[d] = v * invL;
        }
    }
}

// ---------------------------------------------------------------------------
// Inputs (metadata order): 0=x 1=mask 2=cos 3=sin 4=Wq 5=bq 6=Wk 7=bk
//                          8=Wv 9=bv 10=Wo 11=bo
// ---------------------------------------------------------------------------
extern "C" void kernel_launch(void* const* d_in, const int* in_sizes, int n_in,
                              void* d_out, int out_size)
{
    const float* x    = (const float*)d_in[0];
    const float* cosT = (const float*)d_in[2];
    const float* sinT = (const float*)d_in[3];
    const float* Wq   = (const float*)d_in[4];
    const float* bq   = (const float*)d_in[5];
    const float* Wk   = (const float*)d_in[6];
    const float* bk   = (const float*)d_in[7];
    const float* Wv   = (const float*)d_in[8];
    const float* bv   = (const float*)d_in[9];
    const float* Wo   = (const float*)d_in[10];
    const float* bo   = (const float*)d_in[11];
    float* out = (float*)d_out;

    float *qp, *kp, *vp, *ap;
    cudaGetSymbolAddress((void**)&qp, g_q);
    cudaGetSymbolAddress((void**)&kp, g_k);
    cudaGetSymbolAddress((void**)&vp, g_v);
    cudaGetSymbolAddress((void**)&ap, g_a);

    const dim3 gg(N_ / 128, M_ / 128);   // (8, 32)
    gemm_tf32<1><<<gg, 256>>>(x, Wq, bq, qp);
    gemm_tf32<1><<<gg, 256>>>(x, Wk, bk, kp);
    gemm_tf32<1><<<gg, 256>>>(x, Wv, bv, vp);

    rope_kernel<<<(B_*H_*S_*32) / 256, 256>>>(cosT, sinT);

    attn_kernel<<<dim3(S_ / 8, B_ * H_), 128>>>();

    gemm_tf32<0><<<gg, 256>>>(ap, Wo, bo, out);
}

// round 7
// speedup vs baseline: 1.3935x; 1.3517x over previous
#include <cuda_runtime.h>
#include <mma.h>

using namespace nvcuda;

#define B_  2
#define S_  2048
#define E_  1024
#define H_  16
#define D_  64
#define M_  (B_*S_)   /* 4096 */
#define K_  E_        /* 1024 */
#define N_  E_        /* 1024 */

// Scratch (device globals: no allocation allowed)
__device__ float g_q[B_*H_*S_*D_];
__device__ float g_k[B_*H_*S_*D_];
__device__ float g_v[B_*H_*S_*D_];
__device__ float g_a[B_*S_*E_];

// ---------------------------------------------------------------------------
// tf32 tensor-core GEMM body: C[M,N] = A[M,K] @ W[N,K]^T + bias[N]
// Register-prefetch double-buffered k-loop.
// PERM=1 scatters to [B,H,S,D]; PERM=0 row-major.
// ---------------------------------------------------------------------------
template<int PERM>
__device__ __forceinline__
void gemm_body(const float* __restrict__ A, const float* __restrict__ W,
               const float* __restrict__ bias, float* __restrict__ C,
               int m0, int n0)
{
    __shared__ float As[128][36];
    __shared__ float Bs[128][36];
    __shared__ float biasS[16][128];

    const int tid = threadIdx.x;
    const int wid = tid >> 5;
    const int wm  = wid >> 2;
    const int wn  = wid & 3;

    for (int i = tid; i < 16 * 128; i += 256) {
        biasS[i >> 7][i & 127] = bias[n0 + (i & 127)];
    }
    __syncthreads();

    wmma::fragment<wmma::accumulator, 16, 16, 8, float> c_frag[4][2];
    #pragma unroll
    for (int i = 0; i < 4; i++)
        #pragma unroll
        for (int j = 0; j < 2; j++)
            wmma::load_matrix_sync(c_frag[i][j], &biasS[0][wn*32 + j*16], 128,
                                   wmma::mem_row_major);

    wmma::fragment<wmma::matrix_a, 16, 16, 8, wmma::precision::tf32, wmma::row_major> a_frag[4];
    wmma::fragment<wmma::matrix_b, 16, 16, 8, wmma::precision::tf32, wmma::col_major> b_frag[2];

    // per-thread staging indices: 4 (row, c4) pairs covering 128x32 chunk
    float4 pa[4], pb[4];

    #pragma unroll
    for (int it = 0; it < 4; it++) {
        const int f   = tid + it * 256;
        const int row = f >> 3;
        const int c4  = (f & 7) << 2;
        pa[it] = *(const float4*)(A + (size_t)(m0 + row) * K_ + c4);
        pb[it] = *(const float4*)(W + (size_t)(n0 + row) * K_ + c4);
    }

    for (int k0 = 0; k0 < K_; k0 += 32) {
        __syncthreads();
        #pragma unroll
        for (int it = 0; it < 4; it++) {
            const int f   = tid + it * 256;
            const int row = f >> 3;
            const int c4  = (f & 7) << 2;
            float4 av = pa[it];
            av.x = wmma::__float_to_tf32(av.x); av.y = wmma::__float_to_tf32(av.y);
            av.z = wmma::__float_to_tf32(av.z); av.w = wmma::__float_to_tf32(av.w);
            *(float4*)&As[row][c4] = av;
            float4 bv = pb[it];
            bv.x = wmma::__float_to_tf32(bv.x); bv.y = wmma::__float_to_tf32(bv.y);
            bv.z = wmma::__float_to_tf32(bv.z); bv.w = wmma::__float_to_tf32(bv.w);
            *(float4*)&Bs[row][c4] = bv;
        }
        __syncthreads();

        // prefetch next chunk (overlaps with the mma block below)
        if (k0 + 32 < K_) {
            #pragma unroll
            for (int it = 0; it < 4; it++) {
                const int f   = tid + it * 256;
                const int row = f >> 3;
                const int c4  = (f & 7) << 2;
                pa[it] = *(const float4*)(A + (size_t)(m0 + row) * K_ + k0 + 32 + c4);
                pb[it] = *(const float4*)(W + (size_t)(n0 + row) * K_ + k0 + 32 + c4);
            }
        }

        #pragma unroll
        for (int kk = 0; kk < 32; kk += 8) {
            #pragma unroll
            for (int i = 0; i < 4; i++)
                wmma::load_matrix_sync(a_frag[i], &As[wm*64 + i*16][kk], 36);
            #pragma unroll
            for (int j = 0; j < 2; j++)
                wmma::load_matrix_sync(b_frag[j], &Bs[wn*32 + j*16][kk], 36);
            #pragma unroll
            for (int i = 0; i < 4; i++)
                #pragma unroll
                for (int j = 0; j < 2; j++)
                    wmma::mma_sync(c_frag[i][j], a_frag[i], b_frag[j], c_frag[i][j]);
        }
    }

    #pragma unroll
    for (int i = 0; i < 4; i++) {
        const int mt = m0 + wm*64 + i*16;
        #pragma unroll
        for (int j = 0; j < 2; j++) {
            const int nt = n0 + wn*32 + j*16;
            if (PERM) {
                const int b = mt >> 11;
                const int s = mt & (S_ - 1);
                const int h = nt >> 6;
                const int d = nt & 63;
                float* p = C + (((size_t)((b << 4) + h)) * S_ + s) * 64 + d;
                wmma::store_matrix_sync(p, c_frag[i][j], 64, wmma::mem_row_major);
            } else {
                float* p = C + (size_t)mt * N_ + nt;
                wmma::store_matrix_sync(p, c_frag[i][j], N_, wmma::mem_row_major);
            }
        }
    }
}

// Fused QKV projection: blockIdx.z selects (Wq,bq)->g_q, (Wk,bk)->g_k, (Wv,bv)->g_v
__global__ __launch_bounds__(256)
void gemm_qkv(const float* __restrict__ A,
              const float* __restrict__ Wq, const float* __restrict__ bq,
              const float* __restrict__ Wk, const float* __restrict__ bk,
              const float* __restrict__ Wv, const float* __restrict__ bv,
              float* __restrict__ q, float* __restrict__ k, float* __restrict__ v)
{
    const int m0 = blockIdx.y * 128;
    const int n0 = blockIdx.x * 128;
    const int z  = blockIdx.z;
    const float* W  = (z == 0) ? Wq : (z == 1) ? Wk : Wv;
    const float* bb = (z == 0) ? bq : (z == 1) ? bk : bv;
    float*       C  = (z == 0) ? q  : (z == 1) ? k  : v;
    gemm_body<1>(A, W, bb, C, m0, n0);
}

__global__ __launch_bounds__(256)
void gemm_out(const float* __restrict__ A, const float* __restrict__ W,
              const float* __restrict__ bias, float* __restrict__ C)
{
    gemm_body<0>(A, W, bias, C, blockIdx.y * 128, blockIdx.x * 128);
}

// ---------------------------------------------------------------------------
// RoPE applied in-place to g_q and g_k.
// ---------------------------------------------------------------------------
__global__ __launch_bounds__(256)
void rope_kernel(const float* __restrict__ cosT, const float* __restrict__ sinT)
{
    const int idx = blockIdx.x * blockDim.x + threadIdx.x;
    const int d  = idx & 31;
    const int s  = (idx >> 5) & (S_ - 1);
    const int bh = idx >> 16;

    const float c1 = cosT[s*64 + d];
    const float s1 = sinT[s*64 + d];
    const float c2 = cosT[s*64 + d + 32];
    const float s2 = sinT[s*64 + d + 32];

    const size_t base = ((size_t)bh * S_ + s) * 64 + d;

    float q1 = g_q[base], q2 = g_q[base + 32];
    g_q[base]      = q1 * c1 - q2 * s1;
    g_q[base + 32] = q2 * c2 + q1 * s2;

    float k1 = g_k[base], k2 = g_k[base + 32];
    g_k[base]      = k1 * c1 - k2 * s1;
    g_k[base + 32] = k2 * c2 + k1 * s2;
}

// ---------------------------------------------------------------------------
// Tensor-core causal flash attention (tf32 wmma).
// Block = 256 threads (8 warps), 64 query rows, key tiles of 64.
// ---------------------------------------------------------------------------
#define LDS_ 72
#define LOG2E 1.44269504088896f

__global__ __launch_bounds__(256)
void attn_tc()
{
    extern __shared__ float smem[];
    float* sQ   = smem;                 // 64 x 72
    float* sK   = sQ + 64*LDS_;         // 64 x 72
    float* sV   = sK + 64*LDS_;         // 64 x 72
    float* sS   = sV + 64*LDS_;         // 64 x 72 (scores -> P -> PV)
    float* sO   = sS + 64*LDS_;         // 64 x 72
    float* rowm = sO + 64*LDS_;         // 64
    float* rowl = rowm + 64;            // 64
    float* rowc = rowl + 64;            // 64

    const int tid  = threadIdx.x;
    const int w    = tid >> 5;
    const int wq   = w >> 1;            // 0..3 : 16-row strip
    const int wj   = w & 1;             // 0..1 : 32-col strip
    const int bh   = blockIdx.y;
    const int q0   = blockIdx.x * 64;

    const float* Qb = g_q + (size_t)bh * S_ * 64;
    const float* Kb = g_k + (size_t)bh * S_ * 64;
    const float* Vb = g_v + (size_t)bh * S_ * 64;

    // load Q (scaled 1/8, tf32-rounded); zero O; init m/l
    for (int i = tid; i < 64*16; i += 256) {
        const int r = i >> 4, c4 = (i & 15) << 2;
        float4 v = *(const float4*)(Qb + (size_t)(q0 + r) * 64 + c4);
        v.x = wmma::__float_to_tf32(v.x * 0.125f);
        v.y = wmma::__float_to_tf32(v.y * 0.125f);
        v.z = wmma::__float_to_tf32(v.z * 0.125f);
        v.w = wmma::__float_to_tf32(v.w * 0.125f);
        *(float4*)&sQ[r*LDS_ + c4] = v;
        *(float4*)&sO[r*LDS_ + c4] = make_float4(0.f, 0.f, 0.f, 0.f);
    }
    if (tid < 64) { rowm[tid] = -1e30f; rowl[tid] = 0.f; }
    __syncthreads();

    const int ntiles = q0 / 64 + 1;
    for (int t = 0; t < ntiles; t++) {
        const int kb = t * 64;

        // stage K and V tiles (tf32-rounded)
        for (int i = tid; i < 64*16; i += 256) {
            const int r = i >> 4, c4 = (i & 15) << 2;
            float4 kv = *(const float4*)(Kb + (size_t)(kb + r) * 64 + c4);
            kv.x = wmma::__float_to_tf32(kv.x); kv.y = wmma::__float_to_tf32(kv.y);
            kv.z = wmma::__float_to_tf32(kv.z); kv.w = wmma::__float_to_tf32(kv.w);
            *(float4*)&sK[r*LDS_ + c4] = kv;
            float4 vv = *(const float4*)(Vb + (size_t)(kb + r) * 64 + c4);
            vv.x = wmma::__float_to_tf32(vv.x); vv.y = wmma::__float_to_tf32(vv.y);
            vv.z = wmma::__float_to_tf32(vv.z); vv.w = wmma::__float_to_tf32(vv.w);
            *(float4*)&sV[r*LDS_ + c4] = vv;
        }
        __syncthreads();

        // ---- S = Q @ K^T  (16q x 32k per warp) ----
        {
            wmma::fragment<wmma::accumulator, 16, 16, 8, float> c[2];
            wmma::fill_fragment(c[0], 0.f);
            wmma::fill_fragment(c[1], 0.f);
            wmma::fragment<wmma::matrix_a, 16, 16, 8, wmma::precision::tf32, wmma::row_major> a;
            wmma::fragment<wmma::matrix_b, 16, 16, 8, wmma::precision::tf32, wmma::col_major> b;
            #pragma unroll
            for (int kk = 0; kk < 64; kk += 8) {
                wmma::load_matrix_sync(a, &sQ[(wq*16)*LDS_ + kk], LDS_);
                wmma::load_matrix_sync(b, &sK[(wj*32)*LDS_ + kk], LDS_);
                wmma::mma_sync(c[0], a, b, c[0]);
                wmma::load_matrix_sync(b, &sK[(wj*32 + 16)*LDS_ + kk], LDS_);
                wmma::mma_sync(c[1], a, b, c[1]);
            }
            wmma::store_matrix_sync(&sS[(wq*16)*LDS_ + wj*32],      c[0], LDS_, wmma::mem_row_major);
            wmma::store_matrix_sync(&sS[(wq*16)*LDS_ + wj*32 + 16], c[1], LDS_, wmma::mem_row_major);
        }
        __syncthreads();

        // ---- online softmax: 4 threads per row, 16 cols each ----
        {
            const int r   = tid >> 2;
            const int sub = tid & 3;
            const int qrow = q0 + r;
            float* base = &sS[r*LDS_ + sub*16];
            const int cg0 = kb + sub*16;

            float mx = -1e30f;
            #pragma unroll
            for (int c = 0; c < 16; c++) {
                if (cg0 + c <= qrow) mx = fmaxf(mx, base[c]);
            }
            mx = fmaxf(mx, __shfl_xor_sync(0xFFFFFFFFu, mx, 1));
            mx = fmaxf(mx, __shfl_xor_sync(0xFFFFFFFFu, mx, 2));

            const float mold = rowm[r];
            const float mnew = fmaxf(mold, mx);
            float sum = 0.f;
            #pragma unroll
            for (int c = 0; c < 16; c++) {
                float p = (cg0 + c <= qrow)
                        ? exp2f((base[c] - mnew) * LOG2E) : 0.f;
                sum += p;
                base[c] = wmma::__float_to_tf32(p);
            }
            sum += __shfl_xor_sync(0xFFFFFFFFu, sum, 1);
            sum += __shfl_xor_sync(0xFFFFFFFFu, sum, 2);

            if (sub == 0) {
                const float cf = exp2f((mold - mnew) * LOG2E);
                rowc[r] = cf;
                rowl[r] = rowl[r] * cf + sum;
                rowm[r] = mnew;
            }
        }
        __syncthreads();

        // ---- PV = P @ V  (16q x 32d per warp) ----
        {
            wmma::fragment<wmma::accumulator, 16, 16, 8, float> c[2];
            wmma::fill_fragment(c[0], 0.f);
            wmma::fill_fragment(c[1], 0.f);
            wmma::fragment<wmma::matrix_a, 16, 16, 8, wmma::precision::tf32, wmma::row_major> a;
            wmma::fragment<wmma::matrix_b, 16, 16, 8, wmma::precision::tf32, wmma::row_major> b;
            #pragma unroll
            for (int kk = 0; kk < 64; kk += 8) {
                wmma::load_matrix_sync(a, &sS[(wq*16)*LDS_ + kk], LDS_);
                wmma::load_matrix_sync(b, &sV[kk*LDS_ + wj*32], LDS_);
                wmma::mma_sync(c[0], a, b, c[0]);
                wmma::load_matrix_sync(b, &sV[kk*LDS_ + wj*32 + 16], LDS_);
                wmma::mma_sync(c[1], a, b, c[1]);
            }
            __syncthreads();   // all warps done reading P before overwrite
            wmma::store_matrix_sync(&sS[(wq*16)*LDS_ + wj*32],      c[0], LDS_, wmma::mem_row_major);
            wmma::store_matrix_sync(&sS[(wq*16)*LDS_ + wj*32 + 16], c[1], LDS_, wmma::mem_row_major);
        }
        __syncthreads();

        // ---- O = O * c + PV ----
        for (int i = tid; i < 64*64; i += 256) {
            const int r = i >> 6, d = i & 63;
            sO[r*LDS_ + d] = sO[r*LDS_ + d] * rowc[r] + sS[r*LDS_ + d];
        }
        __syncthreads();
    }

    // ---- write O / l to g_a in [B,S,H*D] layout ----
    const int b = bh >> 4;
    const int h = bh & 15;
    for (int i = tid; i < 64*64; i += 256) {
        const int r = i >> 6, d = i & 63;
        g_a[((size_t)b * S_ + (q0 + r)) * E_ + h*64 + d] = sO[r*LDS_ + d] / rowl[r];
    }
}

// ---------------------------------------------------------------------------
// Inputs: 0=x 1=mask 2=cos 3=sin 4=Wq 5=bq 6=Wk 7=bk 8=Wv 9=bv 10=Wo 11=bo
// ---------------------------------------------------------------------------
extern "C" void kernel_launch(void* const* d_in, const int* in_sizes, int n_in,
                              void* d_out, int out_size)
{
    const float* x    = (const float*)d_in[0];
    const float* cosT = (const float*)d_in[2];
    const float* sinT = (const float*)d_in[3];
    const float* Wq   = (const float*)d_in[4];
    const float* bq   = (const float*)d_in[5];
    const float* Wk   = (const float*)d_in[6];
    const float* bk   = (const float*)d_in[7];
    const float* Wv   = (const float*)d_in[8];
    const float* bv   = (const float*)d_in[9];
    const float* Wo   = (const float*)d_in[10];
    const float* bo   = (const float*)d_in[11];
    float* out = (float*)d_out;

    float *qp, *kp, *vp, *ap;
    cudaGetSymbolAddress((void**)&qp, g_q);
    cudaGetSymbolAddress((void**)&kp, g_k);
    cudaGetSymbolAddress((void**)&vp, g_v);
    cudaGetSymbolAddress((void**)&ap, g_a);

    const int attn_smem = (5 * 64 * LDS_ + 3 * 64) * (int)sizeof(float);
    cudaFuncSetAttribute(attn_tc, cudaFuncAttributeMaxDynamicSharedMemorySize, attn_smem);

    gemm_qkv<<<dim3(N_ / 128, M_ / 128, 3), 256>>>(x, Wq, bq, Wk, bk, Wv, bv,
                                                   qp, kp, vp);

    rope_kernel<<<(B_*H_*S_*32) / 256, 256>>>(cosT, sinT);

    attn_tc<<<dim3(S_ / 64, B_ * H_), 256, attn_smem>>>();

    gemm_out<<<dim3(N_ / 128, M_ / 128), 256>>>(ap, Wo, bo, out);
}

// round 10
// speedup vs baseline: 2.8384x; 2.0369x over previous
#include <cuda_runtime.h>
#include <mma.h>
#include <cstdint>

using namespace nvcuda;

#define B_  2
#define S_  2048
#define E_  1024
#define H_  16
#define D_  64
#define M_  (B_*S_)   /* 4096 */
#define K_  E_        /* 1024 */
#define N_  E_        /* 1024 */

// Scratch (device globals: no allocation allowed)
__device__ float g_q[B_*H_*S_*D_];
__device__ float g_k[B_*H_*S_*D_];
__device__ float g_v[B_*H_*S_*D_];
__device__ float g_a[B_*S_*E_];
__device__ float g_xc[M_*K_];        // tf32-rounded x
__device__ float g_wc[4][N_*K_];     // tf32-rounded Wq,Wk,Wv,Wo

// ---------------------------------------------------------------------------
// cp.async helpers
// ---------------------------------------------------------------------------
__device__ __forceinline__ void cp_async16(uint32_t smem, const void* gptr) {
    asm volatile("cp.async.ca.shared.global [%0], [%1], 16;\n"
                 :: "r"(smem), "l"(gptr));
}
__device__ __forceinline__ void cp_commit() {
    asm volatile("cp.async.commit_group;\n");
}
__device__ __forceinline__ void cp_wait0() {
    asm volatile("cp.async.wait_group 0;\n");
}
__device__ __forceinline__ uint32_t smem_u32(const void* p) {
    return (uint32_t)__cvta_generic_to_shared(p);
}

// ---------------------------------------------------------------------------
// One-time tf32 rounding of x and the 4 weight matrices.
// ---------------------------------------------------------------------------
__global__ __launch_bounds__(256)
void conv_tf32(const float* __restrict__ x,
               const float* __restrict__ wq, const float* __restrict__ wk,
               const float* __restrict__ wv, const float* __restrict__ wo)
{
    const int i = blockIdx.x * 256 + threadIdx.x;   // grid covers M_*K_ exactly
    g_xc[i] = wmma::__float_to_tf32(x[i]);
    if (i < N_*K_) {
        g_wc[0][i] = wmma::__float_to_tf32(wq[i]);
        g_wc[1][i] = wmma::__float_to_tf32(wk[i]);
        g_wc[2][i] = wmma::__float_to_tf32(wv[i]);
        g_wc[3][i] = wmma::__float_to_tf32(wo[i]);
    }
}

// ---------------------------------------------------------------------------
// tf32 GEMM: C[M,N] = A[M,K] @ W[N,K]^T + bias[N], inputs pre-rounded.
// 2-stage cp.async double buffer, 256 thr, 128x128 tile, k-chunk 32.
// PERM=1 scatters to [B,H,S,D] (tf32-rounded); PERM=0 row-major fp32.
// ---------------------------------------------------------------------------
#define GLDA 36
#define GEMM_SMEM ((2*128*GLDA*2 + 16*128) * (int)sizeof(float))

template<int PERM>
__device__ __forceinline__
void gemm_body(const float* __restrict__ A, const float* __restrict__ W,
               const float* __restrict__ bias, float* __restrict__ C,
               int m0, int n0)
{
    extern __shared__ float sm[];
    float* As    = sm;                       // [2][128][GLDA]
    float* Bs    = sm + 2*128*GLDA;          // [2][128][GLDA]
    float* biasS = sm + 4*128*GLDA;          // [16][128]

    const int tid = threadIdx.x;
    const int wid = tid >> 5;
    const int wm  = wid >> 2;
    const int wn  = wid & 3;

    const int row = tid >> 3;            // 0..31 per 256-th chunk step
    const int c4  = (tid & 7) << 2;      // 0,4,...,28

    // prefetch chunk 0 into buf 0
    #pragma unroll
    for (int it = 0; it < 4; it++) {
        const int r = row + it * 32;
        cp_async16(smem_u32(&As[r*GLDA + c4]), A + (size_t)(m0 + r) * K_ + c4);
        cp_async16(smem_u32(&Bs[r*GLDA + c4]), W + (size_t)(n0 + r) * K_ + c4);
    }
    cp_commit();

    // stage replicated bias while the first chunk is in flight
    for (int i = tid; i < 16 * 128; i += 256)
        biasS[i] = bias[n0 + (i & 127)];
    __syncthreads();

    wmma::fragment<wmma::accumulator, 16, 16, 8, float> c_frag[4][2];
    #pragma unroll
    for (int i = 0; i < 4; i++)
        #pragma unroll
        for (int j = 0; j < 2; j++)
            wmma::load_matrix_sync(c_frag[i][j], &biasS[wn*32 + j*16], 128,
                                   wmma::mem_row_major);

    wmma::fragment<wmma::matrix_a, 16, 16, 8, wmma::precision::tf32, wmma::row_major> a_frag[4];
    wmma::fragment<wmma::matrix_b, 16, 16, 8, wmma::precision::tf32, wmma::col_major> b_frag[2];

    for (int k0 = 0; k0 < K_; k0 += 32) {
        const int buf = (k0 >> 5) & 1;
        cp_wait0();
        __syncthreads();

        if (k0 + 32 < K_) {
            const int nb = buf ^ 1;
            #pragma unroll
            for (int it = 0; it < 4; it++) {
                const int r = row + it * 32;
                cp_async16(smem_u32(&As[nb*128*GLDA + r*GLDA + c4]),
                           A + (size_t)(m0 + r) * K_ + k0 + 32 + c4);
                cp_async16(smem_u32(&Bs[nb*128*GLDA + r*GLDA + c4]),
                           W + (size_t)(n0 + r) * K_ + k0 + 32 + c4);
            }
            cp_commit();
        }

        const float* Ab = &As[buf*128*GLDA];
        const float* Bb = &Bs[buf*128*GLDA];
        #pragma unroll
        for (int kk = 0; kk < 32; kk += 8) {
            #pragma unroll
            for (int i = 0; i < 4; i++)
                wmma::load_matrix_sync(a_frag[i], Ab + (wm*64 + i*16)*GLDA + kk, GLDA);
            #pragma unroll
            for (int j = 0; j < 2; j++)
                wmma::load_matrix_sync(b_frag[j], Bb + (wn*32 + j*16)*GLDA + kk, GLDA);
            #pragma unroll
            for (int i = 0; i < 4; i++)
                #pragma unroll
                for (int j = 0; j < 2; j++)
                    wmma::mma_sync(c_frag[i][j], a_frag[i], b_frag[j], c_frag[i][j]);
        }
    }

    #pragma unroll
    for (int i = 0; i < 4; i++) {
        const int mt = m0 + wm*64 + i*16;
        #pragma unroll
        for (int j = 0; j < 2; j++) {
            const int nt = n0 + wn*32 + j*16;
            if (PERM) {
                #pragma unroll
                for (int e = 0; e < c_frag[i][j].num_elements; e++)
                    c_frag[i][j].x[e] = wmma::__float_to_tf32(c_frag[i][j].x[e]);
                const int b = mt >> 11;
                const int s = mt & (S_ - 1);
                const int h = nt >> 6;
                const int d = nt & 63;
                float* p = C + (((size_t)((b << 4) + h)) * S_ + s) * 64 + d;
                wmma::store_matrix_sync(p, c_frag[i][j], 64, wmma::mem_row_major);
            } else {
                float* p = C + (size_t)mt * N_ + nt;
                wmma::store_matrix_sync(p, c_frag[i][j], N_, wmma::mem_row_major);
            }
        }
    }
}

__global__ __launch_bounds__(256, 2)
void gemm_qkv(const float* __restrict__ A, const float* __restrict__ Wc,
              const float* __restrict__ bq, const float* __restrict__ bk,
              const float* __restrict__ bv,
              float* __restrict__ q, float* __restrict__ k, float* __restrict__ v)
{
    const int z = blockIdx.z;
    const float* W  = Wc + (size_t)z * N_ * K_;
    const float* bb = (z == 0) ? bq : (z == 1) ? bk : bv;
    float*       C  = (z == 0) ? q  : (z == 1) ? k  : v;
    gemm_body<1>(A, W, bb, C, blockIdx.y * 128, blockIdx.x * 128);
}

__global__ __launch_bounds__(256, 2)
void gemm_out(const float* __restrict__ A, const float* __restrict__ W,
              const float* __restrict__ bias, float* __restrict__ C)
{
    gemm_body<0>(A, W, bias, C, blockIdx.y * 128, blockIdx.x * 128);
}

// ---------------------------------------------------------------------------
// RoPE in-place on g_q, g_k. Folds the 1/8 score scale into Q and rounds
// both outputs to tf32 (consumed only by the tf32 attention mma).
// ---------------------------------------------------------------------------
__global__ __launch_bounds__(256)
void rope_kernel(const float* __restrict__ cosT, const float* __restrict__ sinT)
{
    const int idx = blockIdx.x * blockDim.x + threadIdx.x;
    const int d  = idx & 31;
    const int s  = (idx >> 5) & (S_ - 1);
    const int bh = idx >> 16;

    const float c1 = cosT[s*64 + d];
    const float s1 = sinT[s*64 + d];
    const float c2 = cosT[s*64 + d + 32];
    const float s2 = sinT[s*64 + d + 32];

    const size_t base = ((size_t)bh * S_ + s) * 64 + d;

    float q1 = g_q[base], q2 = g_q[base + 32];
    g_q[base]      = wmma::__float_to_tf32((q1 * c1 - q2 * s1) * 0.125f);
    g_q[base + 32] = wmma::__float_to_tf32((q2 * c2 + q1 * s2) * 0.125f);

    float k1 = g_k[base], k2 = g_k[base + 32];
    g_k[base]      = wmma::__float_to_tf32(k1 * c1 - k2 * s1);
    g_k[base + 32] = wmma::__float_to_tf32(k2 * c2 + k1 * s2);
}

// ---------------------------------------------------------------------------
// FA2 causal attention, PTX mma.m16n8k8 tf32, register-resident O/softmax.
// 128 threads (4 warps), q-tile 64 (16 rows/warp), k-tile 64.
// ---------------------------------------------------------------------------
#define ALD 68
#define LOG2E 1.44269504088896f

#define MMA8(d, a0,a1,a2,a3, b0,b1)                                       \
    asm volatile("mma.sync.aligned.m16n8k8.row.col.f32.tf32.tf32.f32 "    \
        "{%0,%1,%2,%3}, {%4,%5,%6,%7}, {%8,%9}, {%0,%1,%2,%3};"           \
        : "+f"(d[0]), "+f"(d[1]), "+f"(d[2]), "+f"(d[3])                  \
        : "r"(a0), "r"(a1), "r"(a2), "r"(a3), "r"(b0), "r"(b1))

__global__ __launch_bounds__(128, 4)
void attn_fa2()
{
    extern __shared__ float sm[];
    float* sQ = sm;                 // 64 x 68
    float* sK = sQ + 64*ALD;        // 64 x 68
    float* sV = sK + 64*ALD;        // 64 x 68

    const int tid  = threadIdx.x;
    const int w    = tid >> 5;
    const int lane = tid & 31;
    const int g    = lane >> 2;     // 0..7 (row group)
    const int t    = lane & 3;      // 0..3 (thread-in-group)
    const int bh   = blockIdx.y;
    const int q0   = blockIdx.x * 64;
    const int wbase = w * 16;

    const float* Qb = g_q + (size_t)bh * S_ * 64;
    const float* Kb = g_k + (size_t)bh * S_ * 64;
    const float* Vb = g_v + (size_t)bh * S_ * 64;

    // stage Q (already tf32-rounded and 1/8-scaled by rope)
    for (int i = tid; i < 64*16; i += 128) {
        const int r = i >> 4, c4 = (i & 15) << 2;
        *(float4*)&sQ[r*ALD + c4] = *(const float4*)(Qb + (size_t)(q0 + r) * 64 + c4);
    }
    __syncthreads();

    // Q a-fragments for all 8 k-steps (32 regs)
    uint32_t aq[8][4];
    #pragma unroll
    for (int kk = 0; kk < 8; kk++) {
        aq[kk][0] = __float_as_uint(sQ[(wbase + g    )*ALD + kk*8 + t    ]);
        aq[kk][1] = __float_as_uint(sQ[(wbase + g + 8)*ALD + kk*8 + t    ]);
        aq[kk][2] = __float_as_uint(sQ[(wbase + g    )*ALD + kk*8 + t + 4]);
        aq[kk][3] = __float_as_uint(sQ[(wbase + g + 8)*ALD + kk*8 + t + 4]);
    }

    float o[8][4];
    #pragma unroll
    for (int dn = 0; dn < 8; dn++) { o[dn][0]=0.f; o[dn][1]=0.f; o[dn][2]=0.f; o[dn][3]=0.f; }
    float m0 = -1e30f, m1 = -1e30f, l0 = 0.f, l1 = 0.f;

    const int qrow0 = q0 + wbase + g;
    const int qrow1 = qrow0 + 8;
    const int ntiles = q0 / 64 + 1;

    for (int tix = 0; tix < ntiles; tix++) {
        const int kb = tix * 64;
        __syncthreads();   // prior tile fully consumed
        for (int i = tid; i < 64*16; i += 128) {
            const int r = i >> 4, c4 = (i & 15) << 2;
            *(float4*)&sK[r*ALD + c4] = *(const float4*)(Kb + (size_t)(kb + r) * 64 + c4);
            *(float4*)&sV[r*ALD + c4] = *(const float4*)(Vb + (size_t)(kb + r) * 64 + c4);
        }
        __syncthreads();

        // ---- S = Q @ K^T : 8 key-frags x 8 k-steps ----
        float s[8][4];
        #pragma unroll
        for (int n = 0; n < 8; n++) {
            s[n][0]=0.f; s[n][1]=0.f; s[n][2]=0.f; s[n][3]=0.f;
            #pragma unroll
            for (int kk = 0; kk < 8; kk++) {
                const uint32_t b0 = __float_as_uint(sK[(n*8 + g)*ALD + kk*8 + t    ]);
                const uint32_t b1 = __float_as_uint(sK[(n*8 + g)*ALD + kk*8 + t + 4]);
                MMA8(s[n], aq[kk][0], aq[kk][1], aq[kk][2], aq[kk][3], b0, b1);
            }
        }

        // ---- causal mask (diagonal tile only: kb == q0) ----
        if (tix == ntiles - 1) {
            #pragma unroll
            for (int n = 0; n < 8; n++) {
                const int col0 = kb + n*8 + 2*t;
                const int col1 = col0 + 1;
                if (col0 > qrow0) s[n][0] = -1e30f;
                if (col1 > qrow0) s[n][1] = -1e30f;
                if (col0 > qrow1) s[n][2] = -1e30f;
                if (col1 > qrow1) s[n][3] = -1e30f;
            }
        }

        // ---- online softmax in registers ----
        float mx0 = -1e30f, mx1 = -1e30f;
        #pragma unroll
        for (int n = 0; n < 8; n++) {
            mx0 = fmaxf(mx0, fmaxf(s[n][0], s[n][1]));
            mx1 = fmaxf(mx1, fmaxf(s[n][2], s[n][3]));
        }
        mx0 = fmaxf(mx0, __shfl_xor_sync(0xFFFFFFFFu, mx0, 1));
        mx0 = fmaxf(mx0, __shfl_xor_sync(0xFFFFFFFFu, mx0, 2));
        mx1 = fmaxf(mx1, __shfl_xor_sync(0xFFFFFFFFu, mx1, 1));
        mx1 = fmaxf(mx1, __shfl_xor_sync(0xFFFFFFFFu, mx1, 2));

        const float nm0 = fmaxf(m0, mx0);
        const float nm1 = fmaxf(m1, mx1);
        const float cf0 = exp2f((m0 - nm0) * LOG2E);
        const float cf1 = exp2f((m1 - nm1) * LOG2E);
        m0 = nm0; m1 = nm1;

        float sum0 = 0.f, sum1 = 0.f;
        #pragma unroll
        for (int n = 0; n < 8; n++) {
            s[n][0] = wmma::__float_to_tf32(exp2f((s[n][0] - nm0) * LOG2E));
            s[n][1] = wmma::__float_to_tf32(exp2f((s[n][1] - nm0) * LOG2E));
            s[n][2] = wmma::__float_to_tf32(exp2f((s[n][2] - nm1) * LOG2E));
            s[n][3] = wmma::__float_to_tf32(exp2f((s[n][3] - nm1) * LOG2E));
            sum0 += s[n][0] + s[n][1];
            sum1 += s[n][2] + s[n][3];
        }
        sum0 += __shfl_xor_sync(0xFFFFFFFFu, sum0, 1);
        sum0 += __shfl_xor_sync(0xFFFFFFFFu, sum0, 2);
        sum1 += __shfl_xor_sync(0xFFFFFFFFu, sum1, 1);
        sum1 += __shfl_xor_sync(0xFFFFFFFFu, sum1, 2);
        l0 = l0 * cf0 + sum0;
        l1 = l1 * cf1 + sum1;

        // rescale O
        #pragma unroll
        for (int dn = 0; dn < 8; dn++) {
            o[dn][0] *= cf0; o[dn][1] *= cf0;
            o[dn][2] *= cf1; o[dn][3] *= cf1;
        }

        // ---- O += P @ V  (V rows permuted to match P slot layout) ----
        #pragma unroll
        for (int kp = 0; kp < 8; kp++) {
            const uint32_t a0 = __float_as_uint(s[kp][0]);  // (g,   key 2t)
            const uint32_t a1 = __float_as_uint(s[kp][2]);  // (g+8, key 2t)
            const uint32_t a2 = __float_as_uint(s[kp][1]);  // (g,   key 2t+1)
            const uint32_t a3 = __float_as_uint(s[kp][3]);  // (g+8, key 2t+1)
            const int vr0 = (kp*8 + 2*t    ) * ALD;
            const int vr1 = (kp*8 + 2*t + 1) * ALD;
            #pragma unroll
            for (int dn = 0; dn < 8; dn++) {
                const uint32_t b0 = __float_as_uint(sV[vr0 + dn*8 + g]);
                const uint32_t b1 = __float_as_uint(sV[vr1 + dn*8 + g]);
                MMA8(o[dn], a0, a1, a2, a3, b0, b1);
            }
        }
    }

    // ---- epilogue: O/l, tf32-round, write to g_a [B,S,H*D] ----
    const float inv0 = 1.f / l0;
    const float inv1 = 1.f / l1;
    const int b = bh >> 4;
    const int h = bh & 15;
    float* O0 = g_a + ((size_t)b * S_ + qrow0) * E_ + h*64;
    float* O1 = g_a + ((size_t)b * S_ + qrow1) * E_ + h*64;
    #pragma unroll
    for (int dn = 0; dn < 8; dn++) {
        const int col = dn*8 + 2*t;
        float2 v0 = make_float2(wmma::__float_to_tf32(o[dn][0] * inv0),
                                wmma::__float_to_tf32(o[dn][1] * inv0));
        float2 v1 = make_float2(wmma::__float_to_tf32(o[dn][2] * inv1),
                                wmma::__float_to_tf32(o[dn][3] * inv1));
        *(float2*)(O0 + col) = v0;
        *(float2*)(O1 + col) = v1;
    }
}

// ---------------------------------------------------------------------------
// Inputs: 0=x 1=mask 2=cos 3=sin 4=Wq 5=bq 6=Wk 7=bk 8=Wv 9=bv 10=Wo 11=bo
// ---------------------------------------------------------------------------
extern "C" void kernel_launch(void* const* d_in, const int* in_sizes, int n_in,
                              void* d_out, int out_size)
{
    const float* x    = (const float*)d_in[0];
    const float* cosT = (const float*)d_in[2];
    const float* sinT = (const float*)d_in[3];
    const float* Wq   = (const float*)d_in[4];
    const float* bq   = (const float*)d_in[5];
    const float* Wk   = (const float*)d_in[6];
    const float* bk   = (const float*)d_in[7];
    const float* Wv   = (const float*)d_in[8];
    const float* bv   = (const float*)d_in[9];
    const float* Wo   = (const float*)d_in[10];
    const float* bo   = (const float*)d_in[11];
    float* out = (float*)d_out;

    float *qp, *kp, *vp, *ap, *xcp, *wcp;
    cudaGetSymbolAddress((void**)&qp,  g_q);
    cudaGetSymbolAddress((void**)&kp,  g_k);
    cudaGetSymbolAddress((void**)&vp,  g_v);
    cudaGetSymbolAddress((void**)&ap,  g_a);
    cudaGetSymbolAddress((void**)&xcp, g_xc);
    cudaGetSymbolAddress((void**)&wcp, g_wc);

    const int attn_smem = 3 * 64 * ALD * (int)sizeof(float);
    cudaFuncSetAttribute(attn_fa2, cudaFuncAttributeMaxDynamicSharedMemorySize, attn_smem);
    cudaFuncSetAttribute(gemm_qkv, cudaFuncAttributeMaxDynamicSharedMemorySize, GEMM_SMEM);
    cudaFuncSetAttribute(gemm_out, cudaFuncAttributeMaxDynamicSharedMemorySize, GEMM_SMEM);

    conv_tf32<<<(M_*K_) / 256, 256>>>(x, Wq, Wk, Wv, Wo);

    gemm_qkv<<<dim3(N_ / 128, M_ / 128, 3), 256, GEMM_SMEM>>>(
        xcp, wcp, bq, bk, bv, qp, kp, vp);

    rope_kernel<<<(B_*H_*S_*32) / 256, 256>>>(cosT, sinT);

    attn_fa2<<<dim3(S_ / 64, B_ * H_), 128, attn_smem>>>();

    gemm_out<<<dim3(N_ / 128, M_ / 128), 256, GEMM_SMEM>>>(
        ap, wcp + (size_t)3 * N_ * K_, bo, out);
}

// round 12
// speedup vs baseline: 4.6639x; 1.6432x over previous
#include <cuda_runtime.h>
#include <mma.h>
#include <cstdint>

using namespace nvcuda;

#define B_  2
#define S_  2048
#define E_  1024
#define H_  16
#define D_  64
#define M_  (B_*S_)   /* 4096 */
#define K_  E_        /* 1024 */
#define N_  E_        /* 1024 */

// Scratch (device globals: no allocation allowed)
__device__ float g_q[B_*H_*S_*D_];
__device__ float g_k[B_*H_*S_*D_];
__device__ float g_v[B_*H_*S_*D_];
__device__ float g_a[B_*S_*E_];
__device__ float g_xc[M_*K_];        // tf32-rounded x
__device__ float g_wc[4][N_*K_];     // tf32-rounded Wq,Wk,Wv,Wo

// ---------------------------------------------------------------------------
// PTX helpers
// ---------------------------------------------------------------------------
__device__ __forceinline__ void cp_async16(uint32_t smem, const void* gptr) {
    asm volatile("cp.async.ca.shared.global [%0], [%1], 16;\n"
                 :: "r"(smem), "l"(gptr));
}
__device__ __forceinline__ void cp_commit() {
    asm volatile("cp.async.commit_group;\n");
}
__device__ __forceinline__ void cp_wait0() {
    asm volatile("cp.async.wait_group 0;\n");
}
__device__ __forceinline__ uint32_t smem_u32(const void* p) {
    return (uint32_t)__cvta_generic_to_shared(p);
}

#define MMA8(d, a0,a1,a2,a3, b0,b1)                                       \
    asm volatile("mma.sync.aligned.m16n8k8.row.col.f32.tf32.tf32.f32 "    \
        "{%0,%1,%2,%3}, {%4,%5,%6,%7}, {%8,%9}, {%0,%1,%2,%3};"           \
        : "+f"(d[0]), "+f"(d[1]), "+f"(d[2]), "+f"(d[3])                  \
        : "r"(a0), "r"(a1), "r"(a2), "r"(a3), "r"(b0), "r"(b1))

// ldmatrix over float data viewed as b16: each 8x8 b16 sub-matrix = 8x4 float;
// lane(g=l>>2, t=l&3) receives float[g][t] of its sub-matrix.
#define LDSM4(r0,r1,r2,r3,addr)                                           \
    asm volatile("ldmatrix.sync.aligned.m8n8.x4.shared.b16 {%0,%1,%2,%3}, [%4];" \
        : "=r"(r0), "=r"(r1), "=r"(r2), "=r"(r3) : "r"(addr))

// ---------------------------------------------------------------------------
// One-time tf32 rounding of x and the 4 weight matrices.
// ---------------------------------------------------------------------------
__global__ __launch_bounds__(256)
void conv_tf32(const float* __restrict__ x,
               const float* __restrict__ wq, const float* __restrict__ wk,
               const float* __restrict__ wv, const float* __restrict__ wo)
{
    const int i = blockIdx.x * 256 + threadIdx.x;   // grid covers M_*K_ exactly
    g_xc[i] = wmma::__float_to_tf32(x[i]);
    if (i < N_*K_) {
        g_wc[0][i] = wmma::__float_to_tf32(wq[i]);
        g_wc[1][i] = wmma::__float_to_tf32(wk[i]);
        g_wc[2][i] = wmma::__float_to_tf32(wv[i]);
        g_wc[3][i] = wmma::__float_to_tf32(wo[i]);
    }
}

// ---------------------------------------------------------------------------
// tf32 GEMM via PTX mma + ldmatrix: C[M,N] = A[M,K] @ W[N,K]^T + bias[N].
// 2-stage cp.async double buffer, 256 thr (8 warps 2x4), 128x128 tile,
// warp tile 64x32, k-chunk 32. PERM=1 scatters to [B,H,S,D] (tf32-rounded).
// ---------------------------------------------------------------------------
#define GLDA 36
#define GEMM_SMEM (2*2*128*GLDA*(int)sizeof(float))   /* 73728 B */

template<int PERM>
__device__ __forceinline__
void gemm_body(const float* __restrict__ A, const float* __restrict__ W,
               const float* __restrict__ bias, float* __restrict__ C,
               int m0, int n0)
{
    extern __shared__ float sm[];
    float* As = sm;                       // [2][128][GLDA]
    float* Bs = sm + 2*128*GLDA;          // [2][128][GLDA]

    const int tid  = threadIdx.x;
    const int wid  = tid >> 5;
    const int lane = tid & 31;
    const int wm   = wid >> 2;            // 0..1 (64 rows)
    const int wn   = wid & 3;             // 0..3 (32 cols)
    const int g    = lane >> 2;
    const int t    = lane & 3;

    const int row = tid >> 3;             // staging: 0..31
    const int c4  = (tid & 7) << 2;

    // prefetch chunk 0 into buf 0
    #pragma unroll
    for (int it = 0; it < 4; it++) {
        const int r = row + it * 32;
        cp_async16(smem_u32(&As[r*GLDA + c4]), A + (size_t)(m0 + r) * K_ + c4);
        cp_async16(smem_u32(&Bs[r*GLDA + c4]), W + (size_t)(n0 + r) * K_ + c4);
    }
    cp_commit();

    // accumulators, initialized with bias (c0=c2=bias[col], c1=c3=bias[col+1])
    float c[4][4][4];
    #pragma unroll
    for (int j = 0; j < 4; j++) {
        const float2 bv = *(const float2*)&bias[n0 + wn*32 + j*8 + 2*t];
        #pragma unroll
        for (int i = 0; i < 4; i++) {
            c[i][j][0] = bv.x; c[i][j][1] = bv.y;
            c[i][j][2] = bv.x; c[i][j][3] = bv.y;
        }
    }

    // ldmatrix lane address components
    const int aro = wm*64 + ((lane>>3)&1)*8 + (lane&7);   // A row (sub-dependent)
    const int aco = (lane>>4)*4;                          // A col offset
    const int bro = wn*32 + ((lane>>4)&1)*8 + (lane&7);   // B row
    const int bco = ((lane>>3)&1)*4;                      // B col offset

    for (int k0 = 0; k0 < K_; k0 += 32) {
        const int buf = (k0 >> 5) & 1;
        cp_wait0();
        __syncthreads();

        if (k0 + 32 < K_) {
            const int nb = buf ^ 1;
            #pragma unroll
            for (int it = 0; it < 4; it++) {
                const int r = row + it * 32;
                cp_async16(smem_u32(&As[nb*128*GLDA + r*GLDA + c4]),
                           A + (size_t)(m0 + r) * K_ + k0 + 32 + c4);
                cp_async16(smem_u32(&Bs[nb*128*GLDA + r*GLDA + c4]),
                           W + (size_t)(n0 + r) * K_ + k0 + 32 + c4);
            }
            cp_commit();
        }

        const float* Ab = &As[buf*128*GLDA];
        const float* Bb = &Bs[buf*128*GLDA];
        #pragma unroll
        for (int kk = 0; kk < 4; kk++) {
            uint32_t a[4][4], b[4][2];
            #pragma unroll
            for (int i = 0; i < 4; i++)
                LDSM4(a[i][0], a[i][1], a[i][2], a[i][3],
                      smem_u32(&Ab[(aro + i*16)*GLDA + kk*8 + aco]));
            LDSM4(b[0][0], b[0][1], b[1][0], b[1][1],
                  smem_u32(&Bb[bro*GLDA + kk*8 + bco]));
            LDSM4(b[2][0], b[2][1], b[3][0], b[3][1],
                  smem_u32(&Bb[(bro + 16)*GLDA + kk*8 + bco]));
            #pragma unroll
            for (int i = 0; i < 4; i++)
                #pragma unroll
                for (int j = 0; j < 4; j++)
                    MMA8(c[i][j], a[i][0], a[i][1], a[i][2], a[i][3],
                         b[j][0], b[j][1]);
        }
    }

    // epilogue: acc layout c0=C[g][2t], c1=C[g][2t+1], c2=C[g+8][2t], c3=C[g+8][2t+1]
    #pragma unroll
    for (int i = 0; i < 4; i++) {
        const int r0 = m0 + wm*64 + i*16 + g;
        const int r1 = r0 + 8;
        #pragma unroll
        for (int j = 0; j < 4; j++) {
            const int col = n0 + wn*32 + j*8 + 2*t;
            if (PERM) {
                float2 v0 = make_float2(wmma::__float_to_tf32(c[i][j][0]),
                                        wmma::__float_to_tf32(c[i][j][1]));
                float2 v1 = make_float2(wmma::__float_to_tf32(c[i][j][2]),
                                        wmma::__float_to_tf32(c[i][j][3]));
                const int h = col >> 6, d = col & 63;
                const int b0i = r0 >> 11, s0 = r0 & (S_ - 1);
                const int b1i = r1 >> 11, s1 = r1 & (S_ - 1);
                *(float2*)&C[(((size_t)(b0i*16 + h))*S_ + s0)*64 + d] = v0;
                *(float2*)&C[(((size_t)(b1i*16 + h))*S_ + s1)*64 + d] = v1;
            } else {
                *(float2*)&C[(size_t)r0*N_ + col] = make_float2(c[i][j][0], c[i][j][1]);
                *(float2*)&C[(size_t)r1*N_ + col] = make_float2(c[i][j][2], c[i][j][3]);
            }
        }
    }
}

__global__ __launch_bounds__(256, 2)
void gemm_qkv(const float* __restrict__ A, const float* __restrict__ Wc,
              const float* __restrict__ bq, const float* __restrict__ bk,
              const float* __restrict__ bv,
              float* __restrict__ q, float* __restrict__ k, float* __restrict__ v)
{
    const int z = blockIdx.z;
    const float* W  = Wc + (size_t)z * N_ * K_;
    const float* bb = (z == 0) ? bq : (z == 1) ? bk : bv;
    float*       C  = (z == 0) ? q  : (z == 1) ? k  : v;
    gemm_body<1>(A, W, bb, C, blockIdx.y * 128, blockIdx.x * 128);
}

__global__ __launch_bounds__(256, 2)
void gemm_out(const float* __restrict__ A, const float* __restrict__ W,
              const float* __restrict__ bias, float* __restrict__ C)
{
    gemm_body<0>(A, W, bias, C, blockIdx.y * 128, blockIdx.x * 128);
}

// ---------------------------------------------------------------------------
// RoPE in-place on g_q, g_k. Folds the 1/8 score scale into Q and rounds
// both outputs to tf32 (consumed only by the tf32 attention mma).
// ---------------------------------------------------------------------------
__global__ __launch_bounds__(256)
void rope_kernel(const float* __restrict__ cosT, const float* __restrict__ sinT)
{
    const int idx = blockIdx.x * blockDim.x + threadIdx.x;
    const int d  = idx & 31;
    const int s  = (idx >> 5) & (S_ - 1);
    const int bh = idx >> 16;

    const float c1 = cosT[s*64 + d];
    const float s1 = sinT[s*64 + d];
    const float c2 = cosT[s*64 + d + 32];
    const float s2 = sinT[s*64 + d + 32];

    const size_t base = ((size_t)bh * S_ + s) * 64 + d;

    float q1 = g_q[base], q2 = g_q[base + 32];
    g_q[base]      = wmma::__float_to_tf32((q1 * c1 - q2 * s1) * 0.125f);
    g_q[base + 32] = wmma::__float_to_tf32((q2 * c2 + q1 * s2) * 0.125f);

    float k1 = g_k[base], k2 = g_k[base + 32];
    g_k[base]      = wmma::__float_to_tf32(k1 * c1 - k2 * s1);
    g_k[base + 32] = wmma::__float_to_tf32(k2 * c2 + k1 * s2);
}

// ---------------------------------------------------------------------------
// FA2 causal attention, PTX mma.m16n8k8 tf32, register-resident O/softmax.
// 128 threads (4 warps), q-tile 64 (16 rows/warp), k-tile 64.
// S-phase B-fragments via ldmatrix.x4 (4 per key-block instead of 16 LDS).
// ---------------------------------------------------------------------------
#define ALD 68
#define LOG2E 1.44269504088896f

__global__ __launch_bounds__(128, 4)
void attn_fa2()
{
    extern __shared__ float sm[];
    float* sQ = sm;                 // 64 x 68
    float* sK = sQ + 64*ALD;        // 64 x 68
    float* sV = sK + 64*ALD;        // 64 x 68

    const int tid  = threadIdx.x;
    const int w    = tid >> 5;
    const int lane = tid & 31;
    const int g    = lane >> 2;     // 0..7 (row group)
    const int t    = lane & 3;      // 0..3 (thread-in-group)
    const int bh   = blockIdx.y;
    const int q0   = blockIdx.x * 64;
    const int wbase = w * 16;

    const float* Qb = g_q + (size_t)bh * S_ * 64;
    const float* Kb = g_k + (size_t)bh * S_ * 64;
    const float* Vb = g_v + (size_t)bh * S_ * 64;

    // stage Q (already tf32-rounded and 1/8-scaled by rope)
    for (int i = tid; i < 64*16; i += 128) {
        const int r = i >> 4, c4 = (i & 15) << 2;
        *(float4*)&sQ[r*ALD + c4] = *(const float4*)(Qb + (size_t)(q0 + r) * 64 + c4);
    }
    __syncthreads();

    // Q a-fragments for all 8 k-steps (32 regs)
    uint32_t aq[8][4];
    #pragma unroll
    for (int kk = 0; kk < 8; kk++) {
        aq[kk][0] = __float_as_uint(sQ[(wbase + g    )*ALD + kk*8 + t    ]);
        aq[kk][1] = __float_as_uint(sQ[(wbase + g + 8)*ALD + kk*8 + t    ]);
        aq[kk][2] = __float_as_uint(sQ[(wbase + g    )*ALD + kk*8 + t + 4]);
        aq[kk][3] = __float_as_uint(sQ[(wbase + g + 8)*ALD + kk*8 + t + 4]);
    }

    float o[8][4];
    #pragma unroll
    for (int dn = 0; dn < 8; dn++) { o[dn][0]=0.f; o[dn][1]=0.f; o[dn][2]=0.f; o[dn][3]=0.f; }
    float m0 = -1e30f, m1 = -1e30f, l0 = 0.f, l1 = 0.f;

    const int qrow0 = q0 + wbase + g;
    const int qrow1 = qrow0 + 8;
    const int ntiles = q0 / 64 + 1;

    // ldmatrix lane address components for K (S-phase)
    const int krow = lane & 7;
    const int kco  = (lane >> 3) * 4;

    for (int tix = 0; tix < ntiles; tix++) {
        const int kb = tix * 64;
        __syncthreads();   // prior tile fully consumed
        for (int i = tid; i < 64*16; i += 128) {
            const int r = i >> 4, c4 = (i & 15) << 2;
            *(float4*)&sK[r*ALD + c4] = *(const float4*)(Kb + (size_t)(kb + r) * 64 + c4);
            *(float4*)&sV[r*ALD + c4] = *(const float4*)(Vb + (size_t)(kb + r) * 64 + c4);
        }
        __syncthreads();

        // ---- S = Q @ K^T : per key-block, 4 ldmatrix.x4 + 8 MMA8 ----
        float s[8][4];
        #pragma unroll
        for (int n = 0; n < 8; n++) {
            s[n][0]=0.f; s[n][1]=0.f; s[n][2]=0.f; s[n][3]=0.f;
            #pragma unroll
            for (int kp2 = 0; kp2 < 4; kp2++) {
                uint32_t b0a, b1a, b0b, b1b;
                LDSM4(b0a, b1a, b0b, b1b,
                      smem_u32(&sK[(n*8 + krow)*ALD + kp2*16 + kco]));
                MMA8(s[n], aq[2*kp2][0], aq[2*kp2][1], aq[2*kp2][2], aq[2*kp2][3],
                     b0a, b1a);
                MMA8(s[n], aq[2*kp2+1][0], aq[2*kp2+1][1], aq[2*kp2+1][2], aq[2*kp2+1][3],
                     b0b, b1b);
            }
        }

        // ---- causal mask (diagonal tile only: kb == q0) ----
        if (tix == ntiles - 1) {
            #pragma unroll
            for (int n = 0; n < 8; n++) {
                const int col0 = kb + n*8 + 2*t;
                const int col1 = col0 + 1;
                if (col0 > qrow0) s[n][0] = -1e30f;
                if (col1 > qrow0) s[n][1] = -1e30f;
                if (col0 > qrow1) s[n][2] = -1e30f;
                if (col1 > qrow1) s[n][3] = -1e30f;
            }
        }

        // ---- online softmax in registers ----
        float mx0 = -1e30f, mx1 = -1e30f;
        #pragma unroll
        for (int n = 0; n < 8; n++) {
            mx0 = fmaxf(mx0, fmaxf(s[n][0], s[n][1]));
            mx1 = fmaxf(mx1, fmaxf(s[n][2], s[n][3]));
        }
        mx0 = fmaxf(mx0, __shfl_xor_sync(0xFFFFFFFFu, mx0, 1));
        mx0 = fmaxf(mx0, __shfl_xor_sync(0xFFFFFFFFu, mx0, 2));
        mx1 = fmaxf(mx1, __shfl_xor_sync(0xFFFFFFFFu, mx1, 1));
        mx1 = fmaxf(mx1, __shfl_xor_sync(0xFFFFFFFFu, mx1, 2));

        const float nm0 = fmaxf(m0, mx0);
        const float nm1 = fmaxf(m1, mx1);
        const float cf0 = exp2f((m0 - nm0) * LOG2E);
        const float cf1 = exp2f((m1 - nm1) * LOG2E);
        m0 = nm0; m1 = nm1;

        float sum0 = 0.f, sum1 = 0.f;
        #pragma unroll
        for (int n = 0; n < 8; n++) {
            s[n][0] = wmma::__float_to_tf32(exp2f((s[n][0] - nm0) * LOG2E));
            s[n][1] = wmma::__float_to_tf32(exp2f((s[n][1] - nm0) * LOG2E));
            s[n][2] = wmma::__float_to_tf32(exp2f((s[n][2] - nm1) * LOG2E));
            s[n][3] = wmma::__float_to_tf32(exp2f((s[n][3] - nm1) * LOG2E));
            sum0 += s[n][0] + s[n][1];
            sum1 += s[n][2] + s[n][3];
        }
        sum0 += __shfl_xor_sync(0xFFFFFFFFu, sum0, 1);
        sum0 += __shfl_xor_sync(0xFFFFFFFFu, sum0, 2);
        sum1 += __shfl_xor_sync(0xFFFFFFFFu, sum1, 1);
        sum1 += __shfl_xor_sync(0xFFFFFFFFu, sum1, 2);
        l0 = l0 * cf0 + sum0;
        l1 = l1 * cf1 + sum1;

        // rescale O
        #pragma unroll
        for (int dn = 0; dn < 8; dn++) {
            o[dn][0] *= cf0; o[dn][1] *= cf0;
            o[dn][2] *= cf1; o[dn][3] *= cf1;
        }

        // ---- O += P @ V  (V rows permuted to match P slot layout) ----
        #pragma unroll
        for (int kp = 0; kp < 8; kp++) {
            const uint32_t a0 = __float_as_uint(s[kp][0]);  // (g,   key 2t)
            const uint32_t a1 = __float_as_uint(s[kp][2]);  // (g+8, key 2t)
            const uint32_t a2 = __float_as_uint(s[kp][1]);  // (g,   key 2t+1)
            const uint32_t a3 = __float_as_uint(s[kp][3]);  // (g+8, key 2t+1)
            const int vr0 = (kp*8 + 2*t    ) * ALD;
            const int vr1 = (kp*8 + 2*t + 1) * ALD;
            #pragma unroll
            for (int dn = 0; dn < 8; dn++) {
                const uint32_t b0 = __float_as_uint(sV[vr0 + dn*8 + g]);
                const uint32_t b1 = __float_as_uint(sV[vr1 + dn*8 + g]);
                MMA8(o[dn], a0, a1, a2, a3, b0, b1);
            }
        }
    }

    // ---- epilogue: O/l, tf32-round, write to g_a [B,S,H*D] ----
    const float inv0 = 1.f / l0;
    const float inv1 = 1.f / l1;
    const int b = bh >> 4;
    const int h = bh & 15;
    float* O0 = g_a + ((size_t)b * S_ + qrow0) * E_ + h*64;
    float* O1 = g_a + ((size_t)b * S_ + qrow1) * E_ + h*64;
    #pragma unroll
    for (int dn = 0; dn < 8; dn++) {
        const int col = dn*8 + 2*t;
        float2 v0 = make_float2(wmma::__float_to_tf32(o[dn][0] * inv0),
                                wmma::__float_to_tf32(o[dn][1] * inv0));
        float2 v1 = make_float2(wmma::__float_to_tf32(o[dn][2] * inv1),
                                wmma::__float_to_tf32(o[dn][3] * inv1));
        *(float2*)(O0 + col) = v0;
        *(float2*)(O1 + col) = v1;
    }
}

// ---------------------------------------------------------------------------
// Inputs: 0=x 1=mask 2=cos 3=sin 4=Wq 5=bq 6=Wk 7=bk 8=Wv 9=bv 10=Wo 11=bo
// ---------------------------------------------------------------------------
extern "C" void kernel_launch(void* const* d_in, const int* in_sizes, int n_in,
                              void* d_out, int out_size)
{
    const float* x    = (const float*)d_in[0];
    const float* cosT = (const float*)d_in[2];
    const float* sinT = (const float*)d_in[3];
    const float* Wq   = (const float*)d_in[4];
    const float* bq   = (const float*)d_in[5];
    const float* Wk   = (const float*)d_in[6];
    const float* bk   = (const float*)d_in[7];
    const float* Wv   = (const float*)d_in[8];
    const float* bv   = (const float*)d_in[9];
    const float* Wo   = (const float*)d_in[10];
    const float* bo   = (const float*)d_in[11];
    float* out = (float*)d_out;

    float *qp, *kp, *vp, *ap, *xcp, *wcp;
    cudaGetSymbolAddress((void**)&qp,  g_q);
    cudaGetSymbolAddress((void**)&kp,  g_k);
    cudaGetSymbolAddress((void**)&vp,  g_v);
    cudaGetSymbolAddress((void**)&ap,  g_a);
    cudaGetSymbolAddress((void**)&xcp, g_xc);
    cudaGetSymbolAddress((void**)&wcp, g_wc);

    const int attn_smem = 3 * 64 * ALD * (int)sizeof(float);
    cudaFuncSetAttribute(attn_fa2, cudaFuncAttributeMaxDynamicSharedMemorySize, attn_smem);
    cudaFuncSetAttribute(gemm_qkv, cudaFuncAttributeMaxDynamicSharedMemorySize, GEMM_SMEM);
    cudaFuncSetAttribute(gemm_out, cudaFuncAttributeMaxDynamicSharedMemorySize, GEMM_SMEM);

    conv_tf32<<<(M_*K_) / 256, 256>>>(x, Wq, Wk, Wv, Wo);

    gemm_qkv<<<dim3(N_ / 128, M_ / 128, 3), 256, GEMM_SMEM>>>(
        xcp, wcp, bq, bk, bv, qp, kp, vp);

    rope_kernel<<<(B_*H_*S_*32) / 256, 256>>>(cosT, sinT);

    attn_fa2<<<dim3(S_ / 64, B_ * H_), 128, attn_smem>>>();

    gemm_out<<<dim3(N_ / 128, M_ / 128), 256, GEMM_SMEM>>>(
        ap, wcp + (size_t)3 * N_ * K_, bo, out);
}

// round 13
// speedup vs baseline: 4.8177x; 1.0330x over previous
#include <cuda_runtime.h>
#include <mma.h>
#include <cstdint>

using namespace nvcuda;

#define B_  2
#define S_  2048
#define E_  1024
#define H_  16
#define D_  64
#define M_  (B_*S_)   /* 4096 */
#define K_  E_        /* 1024 */
#define N_  E_        /* 1024 */

// Scratch (device globals: no allocation allowed)
__device__ float g_q[B_*H_*S_*D_];
__device__ float g_k[B_*H_*S_*D_];
__device__ float g_v[B_*H_*S_*D_];
__device__ float g_a[B_*S_*E_];
__device__ float g_xc[M_*K_];        // tf32-rounded x
__device__ float g_wc[4][N_*K_];     // tf32-rounded Wq,Wk,Wv,Wo

// ---------------------------------------------------------------------------
// PTX helpers
// ---------------------------------------------------------------------------
__device__ __forceinline__ void cp_async16(uint32_t smem, const void* gptr) {
    asm volatile("cp.async.ca.shared.global [%0], [%1], 16;\n"
                 :: "r"(smem), "l"(gptr));
}
__device__ __forceinline__ void cp_commit() {
    asm volatile("cp.async.commit_group;\n");
}
__device__ __forceinline__ void cp_wait0() {
    asm volatile("cp.async.wait_group 0;\n");
}
__device__ __forceinline__ uint32_t smem_u32(const void* p) {
    return (uint32_t)__cvta_generic_to_shared(p);
}

#define MMA8(d, a0,a1,a2,a3, b0,b1)                                       \
    asm volatile("mma.sync.aligned.m16n8k8.row.col.f32.tf32.tf32.f32 "    \
        "{%0,%1,%2,%3}, {%4,%5,%6,%7}, {%8,%9}, {%0,%1,%2,%3};"           \
        : "+f"(d[0]), "+f"(d[1]), "+f"(d[2]), "+f"(d[3])                  \
        : "r"(a0), "r"(a1), "r"(a2), "r"(a3), "r"(b0), "r"(b1))

// ldmatrix over float data viewed as b16: each 8x8 b16 sub-matrix = 8x4 float;
// lane(g=l>>2, t=l&3) receives float[g][t] of its sub-matrix.
#define LDSM4(r0,r1,r2,r3,addr)                                           \
    asm volatile("ldmatrix.sync.aligned.m8n8.x4.shared.b16 {%0,%1,%2,%3}, [%4];" \
        : "=r"(r0), "=r"(r1), "=r"(r2), "=r"(r3) : "r"(addr))

// ---------------------------------------------------------------------------
// One-time tf32 rounding of x and the 4 weight matrices.
// ---------------------------------------------------------------------------
__global__ __launch_bounds__(256)
void conv_tf32(const float* __restrict__ x,
               const float* __restrict__ wq, const float* __restrict__ wk,
               const float* __restrict__ wv, const float* __restrict__ wo)
{
    const int i = blockIdx.x * 256 + threadIdx.x;   // grid covers M_*K_ exactly
    g_xc[i] = wmma::__float_to_tf32(x[i]);
    if (i < N_*K_) {
        g_wc[0][i] = wmma::__float_to_tf32(wq[i]);
        g_wc[1][i] = wmma::__float_to_tf32(wk[i]);
        g_wc[2][i] = wmma::__float_to_tf32(wv[i]);
        g_wc[3][i] = wmma::__float_to_tf32(wo[i]);
    }
}

// ---------------------------------------------------------------------------
// tf32 GEMM via PTX mma + ldmatrix: C[M,N] = A[M,K] @ W[N,K]^T + bias[N].
// 2-stage cp.async double buffer, 256 thr (8 warps 2x4), 128x128 tile,
// warp tile 64x32, k-chunk 32. PERM=1 scatters to [B,H,S,D] (tf32-rounded).
// ---------------------------------------------------------------------------
#define GLDA 36
#define GEMM_SMEM (2*2*128*GLDA*(int)sizeof(float))   /* 73728 B */

template<int PERM>
__device__ __forceinline__
void gemm_body(const float* __restrict__ A, const float* __restrict__ W,
               const float* __restrict__ bias, float* __restrict__ C,
               int m0, int n0)
{
    extern __shared__ float sm[];
    float* As = sm;                       // [2][128][GLDA]
    float* Bs = sm + 2*128*GLDA;          // [2][128][GLDA]

    const int tid  = threadIdx.x;
    const int wid  = tid >> 5;
    const int lane = tid & 31;
    const int wm   = wid >> 2;            // 0..1 (64 rows)
    const int wn   = wid & 3;             // 0..3 (32 cols)
    const int g    = lane >> 2;
    const int t    = lane & 3;

    const int row = tid >> 3;             // staging: 0..31
    const int c4  = (tid & 7) << 2;

    // prefetch chunk 0 into buf 0
    #pragma unroll
    for (int it = 0; it < 4; it++) {
        const int r = row + it * 32;
        cp_async16(smem_u32(&As[r*GLDA + c4]), A + (size_t)(m0 + r) * K_ + c4);
        cp_async16(smem_u32(&Bs[r*GLDA + c4]), W + (size_t)(n0 + r) * K_ + c4);
    }
    cp_commit();

    // accumulators, initialized with bias (c0=c2=bias[col], c1=c3=bias[col+1])
    float c[4][4][4];
    #pragma unroll
    for (int j = 0; j < 4; j++) {
        const float2 bv = *(const float2*)&bias[n0 + wn*32 + j*8 + 2*t];
        #pragma unroll
        for (int i = 0; i < 4; i++) {
            c[i][j][0] = bv.x; c[i][j][1] = bv.y;
            c[i][j][2] = bv.x; c[i][j][3] = bv.y;
        }
    }

    // ldmatrix lane address components
    const int aro = wm*64 + ((lane>>3)&1)*8 + (lane&7);   // A row (sub-dependent)
    const int aco = (lane>>4)*4;                          // A col offset
    const int bro = wn*32 + ((lane>>4)&1)*8 + (lane&7);   // B row
    const int bco = ((lane>>3)&1)*4;                      // B col offset

    for (int k0 = 0; k0 < K_; k0 += 32) {
        const int buf = (k0 >> 5) & 1;
        cp_wait0();
        __syncthreads();

        if (k0 + 32 < K_) {
            const int nb = buf ^ 1;
            #pragma unroll
            for (int it = 0; it < 4; it++) {
                const int r = row + it * 32;
                cp_async16(smem_u32(&As[nb*128*GLDA + r*GLDA + c4]),
                           A + (size_t)(m0 + r) * K_ + k0 + 32 + c4);
                cp_async16(smem_u32(&Bs[nb*128*GLDA + r*GLDA + c4]),
                           W + (size_t)(n0 + r) * K_ + k0 + 32 + c4);
            }
            cp_commit();
        }

        const float* Ab = &As[buf*128*GLDA];
        const float* Bb = &Bs[buf*128*GLDA];
        #pragma unroll
        for (int kk = 0; kk < 4; kk++) {
            uint32_t a[4][4], b[4][2];
            #pragma unroll
            for (int i = 0; i < 4; i++)
                LDSM4(a[i][0], a[i][1], a[i][2], a[i][3],
                      smem_u32(&Ab[(aro + i*16)*GLDA + kk*8 + aco]));
            LDSM4(b[0][0], b[0][1], b[1][0], b[1][1],
                  smem_u32(&Bb[bro*GLDA + kk*8 + bco]));
            LDSM4(b[2][0], b[2][1], b[3][0], b[3][1],
                  smem_u32(&Bb[(bro + 16)*GLDA + kk*8 + bco]));
            #pragma unroll
            for (int i = 0; i < 4; i++)
                #pragma unroll
                for (int j = 0; j < 4; j++)
                    MMA8(c[i][j], a[i][0], a[i][1], a[i][2], a[i][3],
                         b[j][0], b[j][1]);
        }
    }

    // epilogue: acc layout c0=C[g][2t], c1=C[g][2t+1], c2=C[g+8][2t], c3=C[g+8][2t+1]
    #pragma unroll
    for (int i = 0; i < 4; i++) {
        const int r0 = m0 + wm*64 + i*16 + g;
        const int r1 = r0 + 8;
        #pragma unroll
        for (int j = 0; j < 4; j++) {
            const int col = n0 + wn*32 + j*8 + 2*t;
            if (PERM) {
                float2 v0 = make_float2(wmma::__float_to_tf32(c[i][j][0]),
                                        wmma::__float_to_tf32(c[i][j][1]));
                float2 v1 = make_float2(wmma::__float_to_tf32(c[i][j][2]),
                                        wmma::__float_to_tf32(c[i][j][3]));
                const int h = col >> 6, d = col & 63;
                const int b0i = r0 >> 11, s0 = r0 & (S_ - 1);
                const int b1i = r1 >> 11, s1 = r1 & (S_ - 1);
                *(float2*)&C[(((size_t)(b0i*16 + h))*S_ + s0)*64 + d] = v0;
                *(float2*)&C[(((size_t)(b1i*16 + h))*S_ + s1)*64 + d] = v1;
            } else {
                *(float2*)&C[(size_t)r0*N_ + col] = make_float2(c[i][j][0], c[i][j][1]);
                *(float2*)&C[(size_t)r1*N_ + col] = make_float2(c[i][j][2], c[i][j][3]);
            }
        }
    }
}

__global__ __launch_bounds__(256, 2)
void gemm_qkv(const float* __restrict__ A, const float* __restrict__ Wc,
              const float* __restrict__ bq, const float* __restrict__ bk,
              const float* __restrict__ bv,
              float* __restrict__ q, float* __restrict__ k, float* __restrict__ v)
{
    const int z = blockIdx.z;
    const float* W  = Wc + (size_t)z * N_ * K_;
    const float* bb = (z == 0) ? bq : (z == 1) ? bk : bv;
    float*       C  = (z == 0) ? q  : (z == 1) ? k  : v;
    gemm_body<1>(A, W, bb, C, blockIdx.y * 128, blockIdx.x * 128);
}

__global__ __launch_bounds__(256, 2)
void gemm_out(const float* __restrict__ A, const float* __restrict__ W,
              const float* __restrict__ bias, float* __restrict__ C)
{
    gemm_body<0>(A, W, bias, C, blockIdx.y * 128, blockIdx.x * 128);
}

// ---------------------------------------------------------------------------
// RoPE in-place on g_q, g_k. Folds the 1/8 score scale into Q and rounds
// both outputs to tf32 (consumed only by the tf32 attention mma).
// ---------------------------------------------------------------------------
__global__ __launch_bounds__(256)
void rope_kernel(const float* __restrict__ cosT, const float* __restrict__ sinT)
{
    const int idx = blockIdx.x * blockDim.x + threadIdx.x;
    const int d  = idx & 31;
    const int s  = (idx >> 5) & (S_ - 1);
    const int bh = idx >> 16;

    const float c1 = cosT[s*64 + d];
    const float s1 = sinT[s*64 + d];
    const float c2 = cosT[s*64 + d + 32];
    const float s2 = sinT[s*64 + d + 32];

    const size_t base = ((size_t)bh * S_ + s) * 64 + d;

    float q1 = g_q[base], q2 = g_q[base + 32];
    g_q[base]      = wmma::__float_to_tf32((q1 * c1 - q2 * s1) * 0.125f);
    g_q[base + 32] = wmma::__float_to_tf32((q2 * c2 + q1 * s2) * 0.125f);

    float k1 = g_k[base], k2 = g_k[base + 32];
    g_k[base]      = wmma::__float_to_tf32(k1 * c1 - k2 * s1);
    g_k[base + 32] = wmma::__float_to_tf32(k2 * c2 + k1 * s2);
}

// ---------------------------------------------------------------------------
// FA2 causal attention, PTX mma.m16n8k8 tf32, register-resident O/softmax.
// 128 threads (4 warps), q-tile 64 (16 rows/warp), k-tile 64.
// R13: S-phase loop interchange (ILP), largest-first blocks, cp.async staging.
// ---------------------------------------------------------------------------
#define ALD 68
#define LOG2E 1.44269504088896f

__global__ __launch_bounds__(128, 4)
void attn_fa2()
{
    extern __shared__ float sm[];
    float* sQ = sm;                 // 64 x 68
    float* sK = sQ + 64*ALD;        // 64 x 68
    float* sV = sK + 64*ALD;        // 64 x 68

    const int tid  = threadIdx.x;
    const int w    = tid >> 5;
    const int lane = tid & 31;
    const int g    = lane >> 2;     // 0..7 (row group)
    const int t    = lane & 3;      // 0..3 (thread-in-group)
    const int bh   = blockIdx.y;
    // largest-first: block 0 takes the longest (most k-tiles) q-tile
    const int q0   = (int)(gridDim.x - 1 - blockIdx.x) * 64;
    const int wbase = w * 16;

    const float* Qb = g_q + (size_t)bh * S_ * 64;
    const float* Kb = g_k + (size_t)bh * S_ * 64;
    const float* Vb = g_v + (size_t)bh * S_ * 64;

    // stage Q via cp.async (already tf32-rounded and 1/8-scaled by rope)
    for (int i = tid; i < 64*16; i += 128) {
        const int r = i >> 4, c4 = (i & 15) << 2;
        cp_async16(smem_u32(&sQ[r*ALD + c4]), Qb + (size_t)(q0 + r) * 64 + c4);
    }
    cp_commit();
    cp_wait0();
    __syncthreads();

    // Q a-fragments for all 8 k-steps (32 regs)
    uint32_t aq[8][4];
    #pragma unroll
    for (int kk = 0; kk < 8; kk++) {
        aq[kk][0] = __float_as_uint(sQ[(wbase + g    )*ALD + kk*8 + t    ]);
        aq[kk][1] = __float_as_uint(sQ[(wbase + g + 8)*ALD + kk*8 + t    ]);
        aq[kk][2] = __float_as_uint(sQ[(wbase + g    )*ALD + kk*8 + t + 4]);
        aq[kk][3] = __float_as_uint(sQ[(wbase + g + 8)*ALD + kk*8 + t + 4]);
    }

    float o[8][4];
    #pragma unroll
    for (int dn = 0; dn < 8; dn++) { o[dn][0]=0.f; o[dn][1]=0.f; o[dn][2]=0.f; o[dn][3]=0.f; }
    float m0 = -1e30f, m1 = -1e30f, l0 = 0.f, l1 = 0.f;

    const int qrow0 = q0 + wbase + g;
    const int qrow1 = qrow0 + 8;
    const int ntiles = q0 / 64 + 1;

    // ldmatrix lane address components for K (S-phase)
    const int krow = lane & 7;
    const int kco  = (lane >> 3) * 4;

    for (int tix = 0; tix < ntiles; tix++) {
        const int kb = tix * 64;
        __syncthreads();   // prior tile fully consumed
        for (int i = tid; i < 64*16; i += 128) {
            const int r = i >> 4, c4 = (i & 15) << 2;
            cp_async16(smem_u32(&sK[r*ALD + c4]), Kb + (size_t)(kb + r) * 64 + c4);
            cp_async16(smem_u32(&sV[r*ALD + c4]), Vb + (size_t)(kb + r) * 64 + c4);
        }
        cp_commit();
        cp_wait0();
        __syncthreads();

        // ---- S = Q @ K^T : kp2 outer, n inner (8 independent accumulators) ----
        float s[8][4];
        #pragma unroll
        for (int n = 0; n < 8; n++) { s[n][0]=0.f; s[n][1]=0.f; s[n][2]=0.f; s[n][3]=0.f; }
        #pragma unroll
        for (int kp2 = 0; kp2 < 4; kp2++) {
            #pragma unroll
            for (int n = 0; n < 8; n++) {
                uint32_t b0a, b1a, b0b, b1b;
                LDSM4(b0a, b1a, b0b, b1b,
                      smem_u32(&sK[(n*8 + krow)*ALD + kp2*16 + kco]));
                MMA8(s[n], aq[2*kp2][0], aq[2*kp2][1], aq[2*kp2][2], aq[2*kp2][3],
                     b0a, b1a);
                MMA8(s[n], aq[2*kp2+1][0], aq[2*kp2+1][1], aq[2*kp2+1][2], aq[2*kp2+1][3],
                     b0b, b1b);
            }
        }

        // ---- causal mask (diagonal tile only: kb == q0) ----
        if (tix == ntiles - 1) {
            #pragma unroll
            for (int n = 0; n < 8; n++) {
                const int col0 = kb + n*8 + 2*t;
                const int col1 = col0 + 1;
                if (col0 > qrow0) s[n][0] = -1e30f;
                if (col1 > qrow0) s[n][1] = -1e30f;
                if (col0 > qrow1) s[n][2] = -1e30f;
                if (col1 > qrow1) s[n][3] = -1e30f;
            }
        }

        // ---- online softmax in registers ----
        float mx0 = -1e30f, mx1 = -1e30f;
        #pragma unroll
        for (int n = 0; n < 8; n++) {
            mx0 = fmaxf(mx0, fmaxf(s[n][0], s[n][1]));
            mx1 = fmaxf(mx1, fmaxf(s[n][2], s[n][3]));
        }
        mx0 = fmaxf(mx0, __shfl_xor_sync(0xFFFFFFFFu, mx0, 1));
        mx0 = fmaxf(mx0, __shfl_xor_sync(0xFFFFFFFFu, mx0, 2));
        mx1 = fmaxf(mx1, __shfl_xor_sync(0xFFFFFFFFu, mx1, 1));
        mx1 = fmaxf(mx1, __shfl_xor_sync(0xFFFFFFFFu, mx1, 2));

        const float nm0 = fmaxf(m0, mx0);
        const float nm1 = fmaxf(m1, mx1);
        const float cf0 = exp2f((m0 - nm0) * LOG2E);
        const float cf1 = exp2f((m1 - nm1) * LOG2E);
        m0 = nm0; m1 = nm1;

        float sum0 = 0.f, sum1 = 0.f;
        #pragma unroll
        for (int n = 0; n < 8; n++) {
            s[n][0] = wmma::__float_to_tf32(exp2f((s[n][0] - nm0) * LOG2E));
            s[n][1] = wmma::__float_to_tf32(exp2f((s[n][1] - nm0) * LOG2E));
            s[n][2] = wmma::__float_to_tf32(exp2f((s[n][2] - nm1) * LOG2E));
            s[n][3] = wmma::__float_to_tf32(exp2f((s[n][3] - nm1) * LOG2E));
            sum0 += s[n][0] + s[n][1];
            sum1 += s[n][2] + s[n][3];
        }
        sum0 += __shfl_xor_sync(0xFFFFFFFFu, sum0, 1);
        sum0 += __shfl_xor_sync(0xFFFFFFFFu, sum0, 2);
        sum1 += __shfl_xor_sync(0xFFFFFFFFu, sum1, 1);
        sum1 += __shfl_xor_sync(0xFFFFFFFFu, sum1, 2);
        l0 = l0 * cf0 + sum0;
        l1 = l1 * cf1 + sum1;

        // rescale O
        #pragma unroll
        for (int dn = 0; dn < 8; dn++) {
            o[dn][0] *= cf0; o[dn][1] *= cf0;
            o[dn][2] *= cf1; o[dn][3] *= cf1;
        }

        // ---- O += P @ V  (V rows permuted to match P slot layout) ----
        #pragma unroll
        for (int kp = 0; kp < 8; kp++) {
            const uint32_t a0 = __float_as_uint(s[kp][0]);  // (g,   key 2t)
            const uint32_t a1 = __float_as_uint(s[kp][2]);  // (g+8, key 2t)
            const uint32_t a2 = __float_as_uint(s[kp][1]);  // (g,   key 2t+1)
            const uint32_t a3 = __float_as_uint(s[kp][3]);  // (g+8, key 2t+1)
            const int vr0 = (kp*8 + 2*t    ) * ALD;
            const int vr1 = (kp*8 + 2*t + 1) * ALD;
            #pragma unroll
            for (int dn = 0; dn < 8; dn++) {
                const uint32_t b0 = __float_as_uint(sV[vr0 + dn*8 + g]);
                const uint32_t b1 = __float_as_uint(sV[vr1 + dn*8 + g]);
                MMA8(o[dn], a0, a1, a2, a3, b0, b1);
            }
        }
    }

    // ---- epilogue: O/l, tf32-round, write to g_a [B,S,H*D] ----
    const float inv0 = 1.f / l0;
    const float inv1 = 1.f / l1;
    const int b = bh >> 4;
    const int h = bh & 15;
    float* O0 = g_a + ((size_t)b * S_ + qrow0) * E_ + h*64;
    float* O1 = g_a + ((size_t)b * S_ + qrow1) * E_ + h*64;
    #pragma unroll
    for (int dn = 0; dn < 8; dn++) {
        const int col = dn*8 + 2*t;
        float2 v0 = make_float2(wmma::__float_to_tf32(o[dn][0] * inv0),
                                wmma::__float_to_tf32(o[dn][1] * inv0));
        float2 v1 = make_float2(wmma::__float_to_tf32(o[dn][2] * inv1),
                                wmma::__float_to_tf32(o[dn][3] * inv1));
        *(float2*)(O0 + col) = v0;
        *(float2*)(O1 + col) = v1;
    }
}

// ---------------------------------------------------------------------------
// Inputs: 0=x 1=mask 2=cos 3=sin 4=Wq 5=bq 6=Wk 7=bk 8=Wv 9=bv 10=Wo 11=bo
// ---------------------------------------------------------------------------
extern "C" void kernel_launch(void* const* d_in, const int* in_sizes, int n_in,
                              void* d_out, int out_size)
{
    const float* x    = (const float*)d_in[0];
    const float* cosT = (const float*)d_in[2];
    const float* sinT = (const float*)d_in[3];
    const float* Wq   = (const float*)d_in[4];
    const float* bq   = (const float*)d_in[5];
    const float* Wk   = (const float*)d_in[6];
    const float* bk   = (const float*)d_in[7];
    const float* Wv   = (const float*)d_in[8];
    const float* bv   = (const float*)d_in[9];
    const float* Wo   = (const float*)d_in[10];
    const float* bo   = (const float*)d_in[11];
    float* out = (float*)d_out;

    float *qp, *kp, *vp, *ap, *xcp, *wcp;
    cudaGetSymbolAddress((void**)&qp,  g_q);
    cudaGetSymbolAddress((void**)&kp,  g_k);
    cudaGetSymbolAddress((void**)&vp,  g_v);
    cudaGetSymbolAddress((void**)&ap,  g_a);
    cudaGetSymbolAddress((void**)&xcp, g_xc);
    cudaGetSymbolAddress((void**)&wcp, g_wc);

    const int attn_smem = 3 * 64 * ALD * (int)sizeof(float);
    cudaFuncSetAttribute(attn_fa2, cudaFuncAttributeMaxDynamicSharedMemorySize, attn_smem);
    cudaFuncSetAttribute(gemm_qkv, cudaFuncAttributeMaxDynamicSharedMemorySize, GEMM_SMEM);
    cudaFuncSetAttribute(gemm_out, cudaFuncAttributeMaxDynamicSharedMemorySize, GEMM_SMEM);

    conv_tf32<<<(M_*K_) / 256, 256>>>(x, Wq, Wk, Wv, Wo);

    gemm_qkv<<<dim3(N_ / 128, M_ / 128, 3), 256, GEMM_SMEM>>>(
        xcp, wcp, bq, bk, bv, qp, kp, vp);

    rope_kernel<<<(B_*H_*S_*32) / 256, 256>>>(cosT, sinT);

    attn_fa2<<<dim3(S_ / 64, B_ * H_), 128, attn_smem>>>();

    gemm_out<<<dim3(N_ / 128, M_ / 128), 256, GEMM_SMEM>>>(
        ap, wcp + (size_t)3 * N_ * K_, bo, out);
}

// round 15
// speedup vs baseline: 4.9488x; 1.0272x over previous
#include <cuda_runtime.h>
#include <mma.h>
#include <cstdint>

using namespace nvcuda;

#define B_  2
#define S_  2048
#define E_  1024
#define H_  16
#define D_  64
#define M_  (B_*S_)   /* 4096 */
#define K_  E_        /* 1024 */
#define N_  E_        /* 1024 */

// Scratch (device globals: no allocation allowed)
__device__ float g_q[B_*H_*S_*D_];
__device__ float g_k[B_*H_*S_*D_];
__device__ float g_v[B_*H_*S_*D_];   // V stored TRANSPOSED: [bh][d][s_slot]
__device__ float g_a[B_*S_*E_];
__device__ float g_xc[M_*K_];        // tf32-rounded x
__device__ float g_wc[4][N_*K_];     // tf32-rounded Wq,Wk,Wv,Wo

// ---------------------------------------------------------------------------
// PTX helpers
// ---------------------------------------------------------------------------
__device__ __forceinline__ void cp_async16(uint32_t smem, const void* gptr) {
    asm volatile("cp.async.ca.shared.global [%0], [%1], 16;\n"
                 :: "r"(smem), "l"(gptr));
}
__device__ __forceinline__ void cp_commit() {
    asm volatile("cp.async.commit_group;\n");
}
__device__ __forceinline__ void cp_wait0() {
    asm volatile("cp.async.wait_group 0;\n");
}
__device__ __forceinline__ uint32_t smem_u32(const void* p) {
    return (uint32_t)__cvta_generic_to_shared(p);
}

#define MMA8(d, a0,a1,a2,a3, b0,b1)                                       \
    asm volatile("mma.sync.aligned.m16n8k8.row.col.f32.tf32.tf32.f32 "    \
        "{%0,%1,%2,%3}, {%4,%5,%6,%7}, {%8,%9}, {%0,%1,%2,%3};"           \
        : "+f"(d[0]), "+f"(d[1]), "+f"(d[2]), "+f"(d[3])                  \
        : "r"(a0), "r"(a1), "r"(a2), "r"(a3), "r"(b0), "r"(b1))

// ldmatrix over float data viewed as b16: each 8x8 b16 sub-matrix = 8x4 float;
// lane(g=l>>2, t=l&3) receives float[g][t] of its sub-matrix.
#define LDSM4(r0,r1,r2,r3,addr)                                           \
    asm volatile("ldmatrix.sync.aligned.m8n8.x4.shared.b16 {%0,%1,%2,%3}, [%4];" \
        : "=r"(r0), "=r"(r1), "=r"(r2), "=r"(r3) : "r"(addr))

// ---------------------------------------------------------------------------
// One-time tf32 rounding of x and the 4 weight matrices.
// ---------------------------------------------------------------------------
__global__ __launch_bounds__(256)
void conv_tf32(const float* __restrict__ x,
               const float* __restrict__ wq, const float* __restrict__ wk,
               const float* __restrict__ wv, const float* __restrict__ wo)
{
    const int i = blockIdx.x * 256 + threadIdx.x;   // grid covers M_*K_ exactly
    g_xc[i] = wmma::__float_to_tf32(x[i]);
    if (i < N_*K_) {
        g_wc[0][i] = wmma::__float_to_tf32(wq[i]);
        g_wc[1][i] = wmma::__float_to_tf32(wk[i]);
        g_wc[2][i] = wmma::__float_to_tf32(wv[i]);
        g_wc[3][i] = wmma::__float_to_tf32(wo[i]);
    }
}

// ---------------------------------------------------------------------------
// tf32 GEMM via PTX mma + ldmatrix: C[M,N] = A[M,K] @ W[N,K]^T + bias[N].
// 2-stage cp.async double buffer, 256 thr (8 warps 2x4), 128x128 tile,
// warp tile 64x32, k-chunk 32.
// PERM=0: row-major fp32. PERM=1: [B,H,S,D] scatter (tf32). PERM=2: V
// transposed [bh][d][s_slot] with PV key-slot permutation baked in (tf32).
// ---------------------------------------------------------------------------
#define GLDA 36
#define GEMM_SMEM (2*2*128*GLDA*(int)sizeof(float))   /* 73728 B */

template<int PERM>
__device__ __forceinline__
void gemm_body(const float* __restrict__ A, const float* __restrict__ W,
               const float* __restrict__ bias, float* __restrict__ C,
               int m0, int n0)
{
    extern __shared__ float sm[];
    float* As = sm;                       // [2][128][GLDA]
    float* Bs = sm + 2*128*GLDA;          // [2][128][GLDA]

    const int tid  = threadIdx.x;
    const int wid  = tid >> 5;
    const int lane = tid & 31;
    const int wm   = wid >> 2;            // 0..1 (64 rows)
    const int wn   = wid & 3;             // 0..3 (32 cols)
    const int g    = lane >> 2;
    const int t    = lane & 3;

    const int row = tid >> 3;             // staging: 0..31
    const int c4  = (tid & 7) << 2;

    // prefetch chunk 0 into buf 0
    #pragma unroll
    for (int it = 0; it < 4; it++) {
        const int r = row + it * 32;
        cp_async16(smem_u32(&As[r*GLDA + c4]), A + (size_t)(m0 + r) * K_ + c4);
        cp_async16(smem_u32(&Bs[r*GLDA + c4]), W + (size_t)(n0 + r) * K_ + c4);
    }
    cp_commit();

    // accumulators, initialized with bias (c0=c2=bias[col], c1=c3=bias[col+1])
    float c[4][4][4];
    #pragma unroll
    for (int j = 0; j < 4; j++) {
        const float2 bv = *(const float2*)&bias[n0 + wn*32 + j*8 + 2*t];
        #pragma unroll
        for (int i = 0; i < 4; i++) {
            c[i][j][0] = bv.x; c[i][j][1] = bv.y;
            c[i][j][2] = bv.x; c[i][j][3] = bv.y;
        }
    }

    // ldmatrix lane address components
    const int aro = wm*64 + ((lane>>3)&1)*8 + (lane&7);   // A row (sub-dependent)
    const int aco = (lane>>4)*4;                          // A col offset
    const int bro = wn*32 + ((lane>>4)&1)*8 + (lane&7);   // B row
    const int bco = ((lane>>3)&1)*4;                      // B col offset

    for (int k0 = 0; k0 < K_; k0 += 32) {
        const int buf = (k0 >> 5) & 1;
        cp_wait0();
        __syncthreads();

        if (k0 + 32 < K_) {
            const int nb = buf ^ 1;
            #pragma unroll
            for (int it = 0; it < 4; it++) {
                const int r = row + it * 32;
                cp_async16(smem_u32(&As[nb*128*GLDA + r*GLDA + c4]),
                           A + (size_t)(m0 + r) * K_ + k0 + 32 + c4);
                cp_async16(smem_u32(&Bs[nb*128*GLDA + r*GLDA + c4]),
                           W + (size_t)(n0 + r) * K_ + k0 + 32 + c4);
            }
            cp_commit();
        }

        const float* Ab = &As[buf*128*GLDA];
        const float* Bb = &Bs[buf*128*GLDA];
        #pragma unroll
        for (int kk = 0; kk < 4; kk++) {
            uint32_t a[4][4], b[4][2];
            #pragma unroll
            for (int i = 0; i < 4; i++)
                LDSM4(a[i][0], a[i][1], a[i][2], a[i][3],
                      smem_u32(&Ab[(aro + i*16)*GLDA + kk*8 + aco]));
            LDSM4(b[0][0], b[0][1], b[1][0], b[1][1],
                  smem_u32(&Bb[bro*GLDA + kk*8 + bco]));
            LDSM4(b[2][0], b[2][1], b[3][0], b[3][1],
                  smem_u32(&Bb[(bro + 16)*GLDA + kk*8 + bco]));
            #pragma unroll
            for (int i = 0; i < 4; i++)
                #pragma unroll
                for (int j = 0; j < 4; j++)
                    MMA8(c[i][j], a[i][0], a[i][1], a[i][2], a[i][3],
                         b[j][0], b[j][1]);
        }
    }

    // epilogue: acc layout c0=C[g][2t], c1=C[g][2t+1], c2=C[g+8][2t], c3=C[g+8][2t+1]
    // PERM==2 slot permutation: sig(g) = even ? g/2 : 4+(g-1)/2
    const int sig = (g & 1) ? (4 + (g >> 1)) : (g >> 1);
    #pragma unroll
    for (int i = 0; i < 4; i++) {
        const int r0 = m0 + wm*64 + i*16 + g;
        const int r1 = r0 + 8;
        #pragma unroll
        for (int j = 0; j < 4; j++) {
            const int col = n0 + wn*32 + j*8 + 2*t;
            if (PERM == 1) {
                float2 v0 = make_float2(wmma::__float_to_tf32(c[i][j][0]),
                                        wmma::__float_to_tf32(c[i][j][1]));
                float2 v1 = make_float2(wmma::__float_to_tf32(c[i][j][2]),
                                        wmma::__float_to_tf32(c[i][j][3]));
                const int h = col >> 6, d = col & 63;
                const int b0i = r0 >> 11, s0 = r0 & (S_ - 1);
                const int b1i = r1 >> 11, s1 = r1 & (S_ - 1);
                *(float2*)&C[(((size_t)(b0i*16 + h))*S_ + s0)*64 + d] = v0;
                *(float2*)&C[(((size_t)(b1i*16 + h))*S_ + s1)*64 + d] = v1;
            } else if (PERM == 2) {
                const int h = col >> 6, d = col & 63;
                const int b0i = r0 >> 11, s0 = r0 & (S_ - 1);
                const int b1i = r1 >> 11, s1 = r1 & (S_ - 1);
                const int slot0 = (s0 & ~7) | sig;
                const int slot1 = (s1 & ~7) | sig;
                float* base0 = C + ((size_t)(b0i*16 + h))*64*S_;
                float* base1 = C + ((size_t)(b1i*16 + h))*64*S_;
                base0[(size_t)(d    )*S_ + slot0] = wmma::__float_to_tf32(c[i][j][0]);
                base0[(size_t)(d + 1)*S_ + slot0] = wmma::__float_to_tf32(c[i][j][1]);
                base1[(size_t)(d    )*S_ + slot1] = wmma::__float_to_tf32(c[i][j][2]);
                base1[(size_t)(d + 1)*S_ + slot1] = wmma::__float_to_tf32(c[i][j][3]);
            } else {
                *(float2*)&C[(size_t)r0*N_ + col] = make_float2(c[i][j][0], c[i][j][1]);
                *(float2*)&C[(size_t)r1*N_ + col] = make_float2(c[i][j][2], c[i][j][3]);
            }
        }
    }
}

__global__ __launch_bounds__(256, 2)
void gemm_qkv(const float* __restrict__ A, const float* __restrict__ Wc,
              const float* __restrict__ bq, const float* __restrict__ bk,
              const float* __restrict__ bv,
              float* __restrict__ q, float* __restrict__ k, float* __restrict__ v)
{
    const int z = blockIdx.z;
    const int m0 = blockIdx.y * 128;
    const int n0 = blockIdx.x * 128;
    if (z == 0)      gemm_body<1>(A, Wc,                        bq, q, m0, n0);
    else if (z == 1) gemm_body<1>(A, Wc + (size_t)N_*K_,        bk, k, m0, n0);
    else             gemm_body<2>(A, Wc + (size_t)2*N_*K_,      bv, v, m0, n0);
}

__global__ __launch_bounds__(256, 2)
void gemm_out(const float* __restrict__ A, const float* __restrict__ W,
              const float* __restrict__ bias, float* __restrict__ C)
{
    gemm_body<0>(A, W, bias, C, blockIdx.y * 128, blockIdx.x * 128);
}

// ---------------------------------------------------------------------------
// RoPE in-place on g_q, g_k (V untouched). Folds the 1/8 score scale into Q
// and rounds both outputs to tf32.
// ---------------------------------------------------------------------------
__global__ __launch_bounds__(256)
void rope_kernel(const float* __restrict__ cosT, const float* __restrict__ sinT)
{
    const int idx = blockIdx.x * blockDim.x + threadIdx.x;
    const int d  = idx & 31;
    const int s  = (idx >> 5) & (S_ - 1);
    const int bh = idx >> 16;

    const float c1 = cosT[s*64 + d];
    const float s1 = sinT[s*64 + d];
    const float c2 = cosT[s*64 + d + 32];
    const float s2 = sinT[s*64 + d + 32];

    const size_t base = ((size_t)bh * S_ + s) * 64 + d;

    float q1 = g_q[base], q2 = g_q[base + 32];
    g_q[base]      = wmma::__float_to_tf32((q1 * c1 - q2 * s1) * 0.125f);
    g_q[base + 32] = wmma::__float_to_tf32((q2 * c2 + q1 * s2) * 0.125f);

    float k1 = g_k[base], k2 = g_k[base + 32];
    g_k[base]      = wmma::__float_to_tf32(k1 * c1 - k2 * s1);
    g_k[base + 32] = wmma::__float_to_tf32(k2 * c2 + k1 * s2);
}

// ---------------------------------------------------------------------------
// FA2 causal attention, PTX mma.m16n8k8 tf32, register-resident O/softmax.
// 128 threads (4 warps), q-tile 64 (16 rows/warp), k-tile 64.
// R15: V pre-transposed (+slot-permuted) in gmem -> PV B-fragments via
// ldmatrix (32 LDSM4/tile instead of 128 scalar LDS).
// ---------------------------------------------------------------------------
#define ALD 68
#define LOG2E 1.44269504088896f

__global__ __launch_bounds__(128, 4)
void attn_fa2()
{
    extern __shared__ float sm[];
    float* sQ  = sm;                 // 64 x 68
    float* sK  = sQ + 64*ALD;        // 64 x 68
    float* sVT = sK + 64*ALD;        // 64 x 68  (rows = d, cols = key slots)

    const int tid  = threadIdx.x;
    const int w    = tid >> 5;
    const int lane = tid & 31;
    const int g    = lane >> 2;     // 0..7 (row group)
    const int t    = lane & 3;      // 0..3 (thread-in-group)
    const int bh   = blockIdx.y;
    // largest-first: block 0 takes the longest (most k-tiles) q-tile
    const int q0   = (int)(gridDim.x - 1 - blockIdx.x) * 64;
    const int wbase = w * 16;

    const float* Qb = g_q + (size_t)bh * S_ * 64;
    const float* Kb = g_k + (size_t)bh * S_ * 64;
    const float* Vb = g_v + (size_t)bh * S_ * 64;   // [d][s_slot] layout

    // stage Q via cp.async (already tf32-rounded and 1/8-scaled by rope)
    for (int i = tid; i < 64*16; i += 128) {
        const int r = i >> 4, c4 = (i & 15) << 2;
        cp_async16(smem_u32(&sQ[r*ALD + c4]), Qb + (size_t)(q0 + r) * 64 + c4);
    }
    cp_commit();
    cp_wait0();
    __syncthreads();

    // Q a-fragments for all 8 k-steps (32 regs)
    uint32_t aq[8][4];
    #pragma unroll
    for (int kk = 0; kk < 8; kk++) {
        aq[kk][0] = __float_as_uint(sQ[(wbase + g    )*ALD + kk*8 + t    ]);
        aq[kk][1] = __float_as_uint(sQ[(wbase + g + 8)*ALD + kk*8 + t    ]);
        aq[kk][2] = __float_as_uint(sQ[(wbase + g    )*ALD + kk*8 + t + 4]);
        aq[kk][3] = __float_as_uint(sQ[(wbase + g + 8)*ALD + kk*8 + t + 4]);
    }

    float o[8][4];
    #pragma unroll
    for (int dn = 0; dn < 8; dn++) { o[dn][0]=0.f; o[dn][1]=0.f; o[dn][2]=0.f; o[dn][3]=0.f; }
    float m0 = -1e30f, m1 = -1e30f, l0 = 0.f, l1 = 0.f;

    const int qrow0 = q0 + wbase + g;
    const int qrow1 = qrow0 + 8;
    const int ntiles = q0 / 64 + 1;

    // ldmatrix lane address components
    const int krow = lane & 7;                            // K: row-in-block
    const int kco  = (lane >> 3) * 4;                     // K: col offset
    const int vro  = ((lane>>4)&1)*8 + (lane&7);          // V^T: row-in-16-block
    const int vco  = ((lane>>3)&1)*4;                     // V^T: col offset

    for (int tix = 0; tix < ntiles; tix++) {
        const int kb = tix * 64;
        __syncthreads();   // prior tile fully consumed
        for (int i = tid; i < 64*16; i += 128) {
            const int r = i >> 4, c4 = (i & 15) << 2;
            cp_async16(smem_u32(&sK[r*ALD + c4]),  Kb + (size_t)(kb + r) * 64 + c4);
            cp_async16(smem_u32(&sVT[r*ALD + c4]), Vb + (size_t)r * S_ + kb + c4);
        }
        cp_commit();
        cp_wait0();
        __syncthreads();

        // ---- S = Q @ K^T : kp2 outer, n inner (8 independent accumulators) ----
        float s[8][4];
        #pragma unroll
        for (int n = 0; n < 8; n++) { s[n][0]=0.f; s[n][1]=0.f; s[n][2]=0.f; s[n][3]=0.f; }
        #pragma unroll
        for (int kp2 = 0; kp2 < 4; kp2++) {
            #pragma unroll
            for (int n = 0; n < 8; n++) {
                uint32_t b0a, b1a, b0b, b1b;
                LDSM4(b0a, b1a, b0b, b1b,
                      smem_u32(&sK[(n*8 + krow)*ALD + kp2*16 + kco]));
                MMA8(s[n], aq[2*kp2][0], aq[2*kp2][1], aq[2*kp2][2], aq[2*kp2][3],
                     b0a, b1a);
                MMA8(s[n], aq[2*kp2+1][0], aq[2*kp2+1][1], aq[2*kp2+1][2], aq[2*kp2+1][3],
                     b0b, b1b);
            }
        }

        // ---- causal mask (diagonal tile only: kb == q0) ----
        if (tix == ntiles - 1) {
            #pragma unroll
            for (int n = 0; n < 8; n++) {
                const int col0 = kb + n*8 + 2*t;
                const int col1 = col0 + 1;
                if (col0 > qrow0) s[n][0] = -1e30f;
                if (col1 > qrow0) s[n][1] = -1e30f;
                if (col0 > qrow1) s[n][2] = -1e30f;
                if (col1 > qrow1) s[n][3] = -1e30f;
            }
        }

        // ---- online softmax in registers ----
        float mx0 = -1e30f, mx1 = -1e30f;
        #pragma unroll
        for (int n = 0; n < 8; n++) {
            mx0 = fmaxf(mx0, fmaxf(s[n][0], s[n][1]));
            mx1 = fmaxf(mx1, fmaxf(s[n][2], s[n][3]));
        }
        mx0 = fmaxf(mx0, __shfl_xor_sync(0xFFFFFFFFu, mx0, 1));
        mx0 = fmaxf(mx0, __shfl_xor_sync(0xFFFFFFFFu, mx0, 2));
        mx1 = fmaxf(mx1, __shfl_xor_sync(0xFFFFFFFFu, mx1, 1));
        mx1 = fmaxf(mx1, __shfl_xor_sync(0xFFFFFFFFu, mx1, 2));

        const float nm0 = fmaxf(m0, mx0);
        const float nm1 = fmaxf(m1, mx1);
        const float cf0 = exp2f((m0 - nm0) * LOG2E);
        const float cf1 = exp2f((m1 - nm1) * LOG2E);
        m0 = nm0; m1 = nm1;

        float sum0 = 0.f, sum1 = 0.f;
        #pragma unroll
        for (int n = 0; n < 8; n++) {
            s[n][0] = wmma::__float_to_tf32(exp2f((s[n][0] - nm0) * LOG2E));
            s[n][1] = wmma::__float_to_tf32(exp2f((s[n][1] - nm0) * LOG2E));
            s[n][2] = wmma::__float_to_tf32(exp2f((s[n][2] - nm1) * LOG2E));
            s[n][3] = wmma::__float_to_tf32(exp2f((s[n][3] - nm1) * LOG2E));
            sum0 += s[n][0] + s[n][1];
            sum1 += s[n][2] + s[n][3];
        }
        sum0 += __shfl_xor_sync(0xFFFFFFFFu, sum0, 1);
        sum0 += __shfl_xor_sync(0xFFFFFFFFu, sum0, 2);
        sum1 += __shfl_xor_sync(0xFFFFFFFFu, sum1, 1);
        sum1 += __shfl_xor_sync(0xFFFFFFFFu, sum1, 2);
        l0 = l0 * cf0 + sum0;
        l1 = l1 * cf1 + sum1;

        // rescale O
        #pragma unroll
        for (int dn = 0; dn < 8; dn++) {
            o[dn][0] *= cf0; o[dn][1] *= cf0;
            o[dn][2] *= cf1; o[dn][3] *= cf1;
        }

        // ---- O += P @ V : B-fragments via ldmatrix on V^T (slot-permuted) ----
        #pragma unroll
        for (int kp = 0; kp < 8; kp++) {
            const uint32_t a0 = __float_as_uint(s[kp][0]);
            const uint32_t a1 = __float_as_uint(s[kp][2]);
            const uint32_t a2 = __float_as_uint(s[kp][1]);
            const uint32_t a3 = __float_as_uint(s[kp][3]);
            #pragma unroll
            for (int dn2 = 0; dn2 < 4; dn2++) {
                uint32_t b0, b1, b2, b3;
                LDSM4(b0, b1, b2, b3,
                      smem_u32(&sVT[(dn2*16 + vro)*ALD + kp*8 + vco]));
                MMA8(o[2*dn2],     a0, a1, a2, a3, b0, b1);
                MMA8(o[2*dn2 + 1], a0, a1, a2, a3, b2, b3);
            }
        }
    }

    // ---- epilogue: O/l, tf32-round, write to g_a [B,S,H*D] ----
    const float inv0 = 1.f / l0;
    const float inv1 = 1.f / l1;
    const int b = bh >> 4;
    const int h = bh & 15;
    float* O0 = g_a + ((size_t)b * S_ + qrow0) * E_ + h*64;
    float* O1 = g_a + ((size_t)b * S_ + qrow1) * E_ + h*64;
    #pragma unroll
    for (int dn = 0; dn < 8; dn++) {
        const int col = dn*8 + 2*t;
        float2 v0 = make_float2(wmma::__float_to_tf32(o[dn][0] * inv0),
                                wmma::__float_to_tf32(o[dn][1] * inv0));
        float2 v1 = make_float2(wmma::__float_to_tf32(o[dn][2] * inv1),
                                wmma::__float_to_tf32(o[dn][3] * inv1));
        *(float2*)(O0 + col) = v0;
        *(float2*)(O1 + col) = v1;
    }
}

// ---------------------------------------------------------------------------
// Inputs: 0=x 1=mask 2=cos 3=sin 4=Wq 5=bq 6=Wk 7=bk 8=Wv 9=bv 10=Wo 11=bo
// ---------------------------------------------------------------------------
extern "C" void kernel_launch(void* const* d_in, const int* in_sizes, int n_in,
                              void* d_out, int out_size)
{
    const float* x    = (const float*)d_in[0];
    const float* cosT = (const float*)d_in[2];
    const float* sinT = (const float*)d_in[3];
    const float* Wq   = (const float*)d_in[4];
    const float* bq   = (const float*)d_in[5];
    const float* Wk   = (const float*)d_in[6];
    const float* bk   = (const float*)d_in[7];
    const float* Wv   = (const float*)d_in[8];
    const float* bv   = (const float*)d_in[9];
    const float* Wo   = (const float*)d_in[10];
    const float* bo   = (const float*)d_in[11];
    float* out = (float*)d_out;

    float *qp, *kp, *vp, *ap, *xcp, *wcp;
    cudaGetSymbolAddress((void**)&qp,  g_q);
    cudaGetSymbolAddress((void**)&kp,  g_k);
    cudaGetSymbolAddress((void**)&vp,  g_v);
    cudaGetSymbolAddress((void**)&ap,  g_a);
    cudaGetSymbolAddress((void**)&xcp, g_xc);
    cudaGetSymbolAddress((void**)&wcp, g_wc);

    const int attn_smem = 3 * 64 * ALD * (int)sizeof(float);
    cudaFuncSetAttribute(attn_fa2, cudaFuncAttributeMaxDynamicSharedMemorySize, attn_smem);
    cudaFuncSetAttribute(gemm_qkv, cudaFuncAttributeMaxDynamicSharedMemorySize, GEMM_SMEM);
    cudaFuncSetAttribute(gemm_out, cudaFuncAttributeMaxDynamicSharedMemorySize, GEMM_SMEM);

    conv_tf32<<<(M_*K_) / 256, 256>>>(x, Wq, Wk, Wv, Wo);

    gemm_qkv<<<dim3(N_ / 128, M_ / 128, 3), 256, GEMM_SMEM>>>(
        xcp, wcp, bq, bk, bv, qp, kp, vp);

    rope_kernel<<<(B_*H_*S_*32) / 256, 256>>>(cosT, sinT);

    attn_fa2<<<dim3(S_ / 64, B_ * H_), 128, attn_smem>>>();

    gemm_out<<<dim3(N_ / 128, M_ / 128), 256, GEMM_SMEM>>>(
        ap, wcp + (size_t)3 * N_ * K_, bo, out);
}